// round 1
// baseline (speedup 1.0000x reference)
#include <cuda_runtime.h>
#include <cuda_bf16.h>

// ---------------- problem constants ----------------
#define BB 16
#define LL 4096
#define CC 256
#define DM 128            // d_model
#define DI 256            // d_inner
#define DS 16             // d_state
#define DR 8              // dt_rank
#define KC 4              // conv kernel
#define TT (BB*LL)        // 65536 tokens
#define CH 128            // scan chunk length
#define NC (LL/CH)        // 32 chunks per batch

// ---------------- scratch (device globals; no allocation allowed) ----------------
__device__ float g_H   [(size_t)TT*DM];       // mix output / reused for O1
__device__ float g_XZ  [(size_t)TT*(2*DI)];   // in-proj output (xc_raw | z)
__device__ float g_XC  [(size_t)TT*DI];       // conv+silu output
__device__ float g_DT  [(size_t)TT*DI];       // softplus dt
__device__ float g_DBL [(size_t)TT*40];       // xproj output (dt-rank 0..7 | B 8..23 | C 24..39)
__device__ float g_Y   [(size_t)TT*DI];       // scan output after epilogue
__device__ float g_Hend[(size_t)BB*NC*DI*DS];
__device__ float g_Hin [(size_t)BB*NC*DI*DS];
__device__ float g_S   [(size_t)BB*NC*DI];
__device__ float g_A   [DI*DS];               // A = -exp(A_log)
__device__ int   g_Aflag[DI];                 // 1 if A[d,s] == (s+1)*A[d,0]

// ---------------- packed f32x2 helpers ----------------
__device__ __forceinline__ unsigned long long pack2(float lo, float hi){
    unsigned long long r; asm("mov.b64 %0,{%1,%2};" : "=l"(r) : "f"(lo), "f"(hi)); return r;
}
__device__ __forceinline__ float2 unpack2(unsigned long long v){
    float2 r; asm("mov.b64 {%0,%1},%2;" : "=f"(r.x), "=f"(r.y) : "l"(v)); return r;
}
__device__ __forceinline__ unsigned long long mul2(unsigned long long a, unsigned long long b){
    unsigned long long d; asm("mul.rn.f32x2 %0,%1,%2;" : "=l"(d) : "l"(a), "l"(b)); return d;
}
__device__ __forceinline__ unsigned long long fma2(unsigned long long a, unsigned long long b, unsigned long long c){
    unsigned long long d; asm("fma.rn.f32x2 %0,%1,%2,%3;" : "=l"(d) : "l"(a), "l"(b), "l"(c)); return d;
}

// ---------------- generic fp32 GEMM: C[M,N] = A[M,K] @ B[K,N] (+bias) ----------------
// BM x BN block tile, BK=8, 256 threads, TM x TN per-thread tile, f32x2 accumulation.
template<int BM, int BN, int TM, int TN, bool CONCAT>
__global__ __launch_bounds__(256, 2)
void gemm_f32(const float* __restrict__ A0, const float* __restrict__ A1,
              const float* __restrict__ Bm, const float* __restrict__ bias,
              float* __restrict__ C, int M, int N, int K)
{
    constexpr int BK = 8;
    __shared__ float As[BK][BM + 4];
    __shared__ float Bs[BK][BN + 4];

    const int tid = threadIdx.x;
    const int m0 = blockIdx.x * BM;
    const int n0 = blockIdx.y * BN;
    constexpr int NTN = BN / TN;
    const int tn = tid % NTN;
    const int tm = tid / NTN;

    unsigned long long acc[TM][TN/2];
#pragma unroll
    for (int i = 0; i < TM; i++)
#pragma unroll
        for (int j = 0; j < TN/2; j++) acc[i][j] = 0ULL;

    for (int k0 = 0; k0 < K; k0 += BK) {
        // load A tile (transposed into As[k][m]); k fastest across lanes -> 32B sectors
#pragma unroll
        for (int q = 0; q < (BK*BM)/256; ++q) {
            int e = tid + q*256;
            int kk = e % BK, mm = e / BK;
            int gk = k0 + kk;
            float v;
            if (CONCAT) {
                v = (gk < 256) ? A0[(size_t)(m0+mm)*256 + gk]
                               : A1[(size_t)(m0+mm)*256 + (gk-256)];
            } else {
                v = A0[(size_t)(m0+mm)*K + gk];
            }
            As[kk][mm] = v;
        }
        // load B tile (coalesced across columns)
#pragma unroll
        for (int q = 0; q < (BK*BN)/256; ++q) {
            int e = tid + q*256;
            int cc = e % BN, rr = e / BN;
            int gn = n0 + cc;
            Bs[rr][cc] = (gn < N) ? Bm[(size_t)(k0+rr)*N + gn] : 0.f;
        }
        __syncthreads();

#pragma unroll
        for (int kk = 0; kk < BK; ++kk) {
            float a[TM];
#pragma unroll
            for (int i = 0; i < TM; i += 4) {
                float4 t = *reinterpret_cast<const float4*>(&As[kk][tm*TM + i]);
                a[i] = t.x; a[i+1] = t.y; a[i+2] = t.z; a[i+3] = t.w;
            }
            unsigned long long b2[TN/2];
#pragma unroll
            for (int j = 0; j < TN/2; j += 2) {
                ulonglong2 t = *reinterpret_cast<const ulonglong2*>(&Bs[kk][tn*TN + 2*j]);
                b2[j] = t.x; b2[j+1] = t.y;
            }
#pragma unroll
            for (int i = 0; i < TM; i++) {
                unsigned long long ad = pack2(a[i], a[i]);
#pragma unroll
                for (int j = 0; j < TN/2; j++) acc[i][j] = fma2(ad, b2[j], acc[i][j]);
            }
        }
        __syncthreads();
    }

#pragma unroll
    for (int i = 0; i < TM; i++) {
        int row = m0 + tm*TM + i;
        float* Crow = C + (size_t)row * N;
#pragma unroll
        for (int j = 0; j < TN/2; j++) {
            float2 v = unpack2(acc[i][j]);
            int col = n0 + tn*TN + 2*j;
            if (col < N)     Crow[col]   = v.x + (bias ? bias[col]   : 0.f);
            if (col+1 < N)   Crow[col+1] = v.y + (bias ? bias[col+1] : 0.f);
        }
    }
}

// ---------------- A_log preprocessing: A = -exp(A_log); detect A[d,s]=(s+1)*A[d,0] ----------------
__global__ void aprep_kernel(const float* __restrict__ A_log)
{
    int d = threadIdx.x;
    if (d >= DI) return;
    float Av[DS];
#pragma unroll
    for (int s = 0; s < DS; s++) {
        Av[s] = -__expf(A_log[d*DS + s]);
        g_A[d*DS + s] = Av[s];
    }
    int ok = 1;
#pragma unroll
    for (int s = 0; s < DS; s++) {
        float tgt = Av[0] * (float)(s+1);
        if (fabsf(Av[s] - tgt) > 1e-5f * fabsf(Av[s]) + 1e-7f) ok = 0;
    }
    g_Aflag[d] = ok;
}

// ---------------- depthwise conv (K=4, causal) + SiLU ----------------
__global__ __launch_bounds__(256)
void conv_silu_kernel(const float* __restrict__ conv_w, const float* __restrict__ conv_b)
{
    int idx = blockIdx.x * 256 + threadIdx.x;   // over T*DI
    int d = idx & (DI-1);
    int t = idx >> 8;
    int l = t & (LL-1);
    float acc = conv_b[d];
#pragma unroll
    for (int k = 0; k < KC; k++) {
        int lt = l - (KC-1) + k;
        if (lt >= 0) acc += g_XZ[(size_t)(t - (KC-1) + k)*(2*DI) + d] * conv_w[d*KC + k];
    }
    float sig = 1.f / (1.f + __expf(-acc));
    g_XC[idx] = acc * sig;
}

// ---------------- dt = softplus(dbl[:, :8] @ W_dt + b_dt) ----------------
__global__ __launch_bounds__(256)
void dt_kernel(const float* __restrict__ W_dt, const float* __restrict__ b_dt)
{
    int idx = blockIdx.x * 256 + threadIdx.x;   // over T*DI
    int d = idx & (DI-1);
    int t = idx >> 8;
    float acc = b_dt[d];
    const float* dbl = g_DBL + (size_t)t*40;
#pragma unroll
    for (int r = 0; r < DR; r++) acc += dbl[r] * W_dt[r*DI + d];
    float sp = (acc > 20.f) ? acc : log1pf(__expf(acc));
    g_DT[idx] = sp;
}

// ---------------- scan pass 1: per-chunk local scan (h_in = 0), record h_end and sum(dt) ----------------
__global__ __launch_bounds__(256)
void scan_pass1()
{
    __shared__ float sB[CH][DS];
    const int bc = blockIdx.x;            // b*NC + c
    const int b = bc / NC, c = bc % NC;
    const int d = threadIdx.x;
    const int tok0 = b*LL + c*CH;

#pragma unroll
    for (int q = 0; q < (CH*DS)/256; q++) {
        int e = threadIdx.x + q*256;
        int j = e % DS, st = e / DS;
        sB[st][j] = g_DBL[(size_t)(tok0+st)*40 + 8 + j];
    }
    __syncthreads();

    const float A0 = g_A[d*DS];
    const int fast = g_Aflag[d];
    float S = 0.f;

    if (fast) {
        unsigned long long h2[DS/2];
#pragma unroll
        for (int sp = 0; sp < DS/2; sp++) h2[sp] = 0ULL;
        for (int st = 0; st < CH; st++) {
            int idx = (tok0+st)*DI + d;
            float dt = g_DT[idx];
            float x  = g_XC[idx];
            S += dt;
            float e1 = __expf(dt * A0);
            float e2 = e1 * e1;
            unsigned long long p2  = pack2(e1, e2);
            unsigned long long e22 = pack2(e2, e2);
            float dtx = dt * x;
            unsigned long long dtx2 = pack2(dtx, dtx);
            const unsigned long long* Bp = reinterpret_cast<const unsigned long long*>(sB[st]);
#pragma unroll
            for (int sp = 0; sp < DS/2; sp++) {
                h2[sp] = fma2(p2, h2[sp], mul2(dtx2, Bp[sp]));
                p2 = mul2(p2, e22);
            }
        }
        float* He = g_Hend + ((size_t)bc*DI + d)*DS;
#pragma unroll
        for (int sp = 0; sp < DS/2; sp++) {
            float2 v = unpack2(h2[sp]);
            He[2*sp] = v.x; He[2*sp+1] = v.y;
        }
    } else {
        float Av[DS], h[DS];
#pragma unroll
        for (int s = 0; s < DS; s++) { Av[s] = g_A[d*DS + s]; h[s] = 0.f; }
        for (int st = 0; st < CH; st++) {
            int idx = (tok0+st)*DI + d;
            float dt = g_DT[idx];
            float x  = g_XC[idx];
            S += dt;
            float dtx = dt * x;
#pragma unroll
            for (int s = 0; s < DS; s++) {
                float a = __expf(dt * Av[s]);
                h[s] = a*h[s] + dtx * sB[st][s];
            }
        }
        float* He = g_Hend + ((size_t)bc*DI + d)*DS;
#pragma unroll
        for (int s = 0; s < DS; s++) He[s] = h[s];
    }
    g_S[(size_t)bc*DI + d] = S;
}

// ---------------- inter-chunk combine: h_in[c+1] = exp(A_s * S_c) * h_in[c] + h_end[c] ----------------
__global__ __launch_bounds__(256)
void scan_combine()
{
    int g = blockIdx.x * 256 + threadIdx.x;   // over BB*DI*DS = 65536
    int s = g & (DS-1);
    int d = (g >> 4) & (DI-1);
    int b = g >> 12;
    float Av = g_A[d*DS + s];
    float h = 0.f;
    for (int c = 0; c < NC; c++) {
        size_t base = ((size_t)(b*NC + c)*DI + d)*DS + s;
        g_Hin[base] = h;
        float S = g_S[(size_t)(b*NC + c)*DI + d];
        h = __expf(Av * S) * h + g_Hend[base];
    }
}

// ---------------- scan pass 2: replay with correct h_in, emit y=(scan + xc*D)*silu(z) ----------------
__global__ __launch_bounds__(256)
void scan_pass2(const float* __restrict__ D_param)
{
    __shared__ float sBC[CH][2*DS];
    const int bc = blockIdx.x;
    const int b = bc / NC, c = bc % NC;
    const int d = threadIdx.x;
    const int tok0 = b*LL + c*CH;

#pragma unroll
    for (int q = 0; q < (CH*2*DS)/256; q++) {
        int e = threadIdx.x + q*256;
        int j = e & (2*DS - 1), st = e >> 5;
        sBC[st][j] = g_DBL[(size_t)(tok0+st)*40 + 8 + j];   // B cols 8..23, C cols 24..39
    }
    __syncthreads();

    const float A0 = g_A[d*DS];
    const int fast = g_Aflag[d];
    const float Dp = D_param[d];
    const size_t hbase = ((size_t)bc*DI + d)*DS;

    if (fast) {
        unsigned long long h2[DS/2];
#pragma unroll
        for (int sp = 0; sp < DS/2; sp++)
            h2[sp] = pack2(g_Hin[hbase + 2*sp], g_Hin[hbase + 2*sp + 1]);
        for (int st = 0; st < CH; st++) {
            int idx = (tok0+st)*DI + d;
            float dt = g_DT[idx];
            float x  = g_XC[idx];
            float e1 = __expf(dt * A0);
            float e2 = e1 * e1;
            unsigned long long p2  = pack2(e1, e2);
            unsigned long long e22 = pack2(e2, e2);
            float dtx = dt * x;
            unsigned long long dtx2 = pack2(dtx, dtx);
            const unsigned long long* BCp = reinterpret_cast<const unsigned long long*>(sBC[st]);
            unsigned long long y2 = 0ULL;
#pragma unroll
            for (int sp = 0; sp < DS/2; sp++) {
                h2[sp] = fma2(p2, h2[sp], mul2(dtx2, BCp[sp]));
                y2 = fma2(h2[sp], BCp[DS/2 + sp], y2);
                p2 = mul2(p2, e22);
            }
            float2 yv = unpack2(y2);
            float y = yv.x + yv.y;
            float z = g_XZ[(size_t)(tok0+st)*(2*DI) + DI + d];
            float sz = z / (1.f + __expf(-z));
            g_Y[idx] = (y + x*Dp) * sz;
        }
    } else {
        float Av[DS], h[DS];
#pragma unroll
        for (int s = 0; s < DS; s++) { Av[s] = g_A[d*DS + s]; h[s] = g_Hin[hbase + s]; }
        for (int st = 0; st < CH; st++) {
            int idx = (tok0+st)*DI + d;
            float dt = g_DT[idx];
            float x  = g_XC[idx];
            float dtx = dt * x;
            float y = 0.f;
#pragma unroll
            for (int s = 0; s < DS; s++) {
                float a = __expf(dt * Av[s]);
                h[s] = a*h[s] + dtx * sBC[st][s];
                y += h[s] * sBC[st][DS + s];
            }
            float z = g_XZ[(size_t)(tok0+st)*(2*DI) + DI + d];
            float sz = z / (1.f + __expf(-z));
            g_Y[idx] = (y + x*Dp) * sz;
        }
    }
}

// ---------------- host launch ----------------
extern "C" void kernel_launch(void* const* d_in, const int* in_sizes, int n_in,
                              void* d_out, int out_size)
{
    const float* x      = (const float*)d_in[0];
    const float* qk     = (const float*)d_in[1];
    const float* W_mix  = (const float*)d_in[2];
    const float* b_mix  = (const float*)d_in[3];
    const float* W_in   = (const float*)d_in[4];
    const float* b_in   = (const float*)d_in[5];
    const float* conv_w = (const float*)d_in[6];
    const float* conv_b = (const float*)d_in[7];
    const float* W_xproj= (const float*)d_in[8];
    const float* W_dt   = (const float*)d_in[9];
    const float* b_dt   = (const float*)d_in[10];
    const float* A_log  = (const float*)d_in[11];
    const float* D_param= (const float*)d_in[12];
    const float* W_op   = (const float*)d_in[13];
    const float* b_op   = (const float*)d_in[14];
    const float* W_out  = (const float*)d_in[15];
    const float* b_out  = (const float*)d_in[16];
    float* out = (float*)d_out;

    float *pH, *pXZ, *pXC, *pDBL, *pY;
    cudaGetSymbolAddress((void**)&pH,  g_H);
    cudaGetSymbolAddress((void**)&pXZ, g_XZ);
    cudaGetSymbolAddress((void**)&pXC, g_XC);
    cudaGetSymbolAddress((void**)&pDBL,g_DBL);
    cudaGetSymbolAddress((void**)&pY,  g_Y);

    // 0) A preprocessing
    aprep_kernel<<<1, 256>>>(A_log);

    // 1) H = [x|qk] @ W_mix + b_mix          (M=T, N=128, K=512)
    gemm_f32<128,128,8,8,true><<<dim3(TT/128, 1), 256>>>(x, qk, W_mix, b_mix, pH, TT, DM, 2*CC);

    // 2) XZ = H @ W_in + b_in                (M=T, N=512, K=128)
    gemm_f32<128,128,8,8,false><<<dim3(TT/128, 4), 256>>>(pH, nullptr, W_in, b_in, pXZ, TT, 2*DI, DM);

    // 3) conv + silu -> XC
    conv_silu_kernel<<<(TT*DI)/256, 256>>>(conv_w, conv_b);

    // 4) DBL = XC @ W_xproj                  (M=T, N=40, K=256)
    gemm_f32<128,64,4,8,false><<<dim3(TT/128, 1), 256>>>(pXC, nullptr, W_xproj, nullptr, pDBL, TT, DR + 2*DS, DI);

    // 5) dt = softplus(DBL[:, :8] @ W_dt + b_dt)
    dt_kernel<<<(TT*DI)/256, 256>>>(W_dt, b_dt);

    // 6-8) chunked selective scan + epilogue
    scan_pass1 <<<BB*NC, 256>>>();
    scan_combine<<< (BB*DI*DS)/256, 256>>>();
    scan_pass2 <<<BB*NC, 256>>>(D_param);

    // 9) O1 = Y @ W_op + b_op                (M=T, N=128, K=256)  (reuse g_H)
    gemm_f32<128,128,8,8,false><<<dim3(TT/128, 1), 256>>>(pY, nullptr, W_op, b_op, pH, TT, DM, DI);

    // 10) out = O1 @ W_out + b_out           (M=T, N=256, K=128)
    gemm_f32<128,128,8,8,false><<<dim3(TT/128, 2), 256>>>(pH, nullptr, W_out, b_out, out, TT, CC, DM);
}

// round 5
// speedup vs baseline: 1.3313x; 1.3313x over previous
#include <cuda_runtime.h>
#include <cuda_bf16.h>
#include <cstdint>

// ---------------- problem constants ----------------
#define BB 16
#define LL 4096
#define CC 256
#define DM 128            // d_model
#define DI 256            // d_inner
#define DS 16             // d_state
#define DR 8              // dt_rank
#define KCV 4             // conv kernel
#define TT (BB*LL)        // 65536 tokens
#define CH 128            // scan chunk length
#define NC (LL/CH)        // 32 chunks per batch

// ---------------- scratch (device globals; no allocation allowed) ----------------
__device__ __align__(16) __nv_bfloat16 g_mixAh[(size_t)TT*512];
__device__ __align__(16) __nv_bfloat16 g_mixAl[(size_t)TT*512];
__device__ __align__(16) __nv_bfloat16 g_Hh[(size_t)TT*DM];
__device__ __align__(16) __nv_bfloat16 g_Hl[(size_t)TT*DM];
__device__ float g_XZ [(size_t)TT*(2*DI)];
__device__ float g_XC [(size_t)TT*DI];
__device__ __align__(16) __nv_bfloat16 g_XCh[(size_t)TT*DI];
__device__ __align__(16) __nv_bfloat16 g_XCl[(size_t)TT*DI];
__device__ float g_DBL[(size_t)TT*40];
__device__ float g_DT [(size_t)TT*DI];
__device__ __align__(16) __nv_bfloat16 g_Yh[(size_t)TT*DI];
__device__ __align__(16) __nv_bfloat16 g_Yl[(size_t)TT*DI];
__device__ __align__(16) __nv_bfloat16 g_O1h[(size_t)TT*DM];
__device__ __align__(16) __nv_bfloat16 g_O1l[(size_t)TT*DM];
// transposed + split weights: Wt[n,k] = W[k,n]
__device__ __align__(16) __nv_bfloat16 g_Wmix_h[DM*512],  g_Wmix_l[DM*512];
__device__ __align__(16) __nv_bfloat16 g_Win_h [512*DM],  g_Win_l [512*DM];
__device__ __align__(16) __nv_bfloat16 g_Wxp_h [64*DI],   g_Wxp_l [64*DI];
__device__ __align__(16) __nv_bfloat16 g_Wop_h [DM*DI],   g_Wop_l [DM*DI];
__device__ __align__(16) __nv_bfloat16 g_Wout_h[CC*DM],   g_Wout_l[CC*DM];
// scan scratch
__device__ float g_Hend[(size_t)BB*NC*DI*DS];
__device__ float g_Hin [(size_t)BB*NC*DI*DS];
__device__ float g_S   [(size_t)BB*NC*DI];
__device__ float g_A   [DI*DS];
__device__ int   g_Aflag[DI];

// ---------------- PTX helpers (sm_80-compatible; no 'a'-suffix features) ----------------
__device__ __forceinline__ uint32_t smem_to_u32(const void* p) {
    uint32_t a;
    asm("{ .reg .u64 t; cvta.to.shared.u64 t, %1; cvt.u32.u64 %0, t; }" : "=r"(a) : "l"(p));
    return a;
}
__device__ __forceinline__ void cp16(uint32_t s, const void* g) {
    asm volatile("cp.async.cg.shared.global [%0], [%1], 16;" :: "r"(s), "l"(g));
}
#define CP_COMMIT() asm volatile("cp.async.commit_group;" ::: "memory")
#define CP_WAIT(n)  asm volatile("cp.async.wait_group %0;" :: "n"(n) : "memory")

#define LDSM_X4(r, addr) \
    asm volatile("ldmatrix.sync.aligned.m8n8.x4.shared.b16 {%0,%1,%2,%3}, [%4];" \
        : "=r"((r)[0]), "=r"((r)[1]), "=r"((r)[2]), "=r"((r)[3]) : "r"(addr))

#define MMA16816(d, a, b0, b1) \
    asm volatile("mma.sync.aligned.m16n8k16.row.col.f32.bf16.bf16.f32 " \
        "{%0,%1,%2,%3}, {%4,%5,%6,%7}, {%8,%9}, {%0,%1,%2,%3};" \
        : "+f"((d)[0]), "+f"((d)[1]), "+f"((d)[2]), "+f"((d)[3]) \
        : "r"((a)[0]), "r"((a)[1]), "r"((a)[2]), "r"((a)[3]), "r"(b0), "r"(b1))

// ---------------- packed f32x2 helpers (scan) ----------------
__device__ __forceinline__ unsigned long long pack2(float lo, float hi){
    unsigned long long r; asm("mov.b64 %0,{%1,%2};" : "=l"(r) : "f"(lo), "f"(hi)); return r;
}
__device__ __forceinline__ float2 unpack2(unsigned long long v){
    float2 r; asm("mov.b64 {%0,%1},%2;" : "=f"(r.x), "=f"(r.y) : "l"(v)); return r;
}
__device__ __forceinline__ unsigned long long mul2(unsigned long long a, unsigned long long b){
    unsigned long long d; asm("mul.rn.f32x2 %0,%1,%2;" : "=l"(d) : "l"(a), "l"(b)); return d;
}
__device__ __forceinline__ unsigned long long fma2(unsigned long long a, unsigned long long b, unsigned long long c){
    unsigned long long d; asm("fma.rn.f32x2 %0,%1,%2,%3;" : "=l"(d) : "l"(a), "l"(b), "l"(c)); return d;
}

__device__ __forceinline__ void split_bf16(float v, __nv_bfloat16& h, __nv_bfloat16& l) {
    h = __float2bfloat16(v);
    l = __float2bfloat16(v - __bfloat162float(h));
}

// =====================================================================
// mma.sync split-bf16 GEMM: C[m,n] = sum_k A[m,k]*Wt[n,k] + bias[n]
// A = Ah+Al (bf16 split, row-major [M,K]); Wt = Bh+Bl ([NTpad,K]).
// 3 passes: Ah*Bh + Al*Bh + Ah*Bl accumulated in fp32 registers.
// CTA: 128 x NT tile, 8 warps (2x4), warp tile 64 x NT/4.
// BK=32, cp.async double-buffered, 40-elem padded smem rows (ldmatrix
// conflict-free: 20r mod 32 distinct for r=0..7).
// =====================================================================
template<int NT, bool WF32, bool WSPLIT>
__global__ __launch_bounds__(256)
void gemm_mma(const __nv_bfloat16* __restrict__ Ah, const __nv_bfloat16* __restrict__ Al,
              const __nv_bfloat16* __restrict__ Bh, const __nv_bfloat16* __restrict__ Bl,
              const float* __restrict__ bias,
              float* __restrict__ Cf, __nv_bfloat16* __restrict__ Chi, __nv_bfloat16* __restrict__ Clo,
              int K, int Nout, int Nclip)
{
    constexpr int NTW = NT / 4;          // warp n-tile: 32 (NT=128) or 16 (NT=64)
    constexpr int NF  = NTW / 8;         // n-frags per warp: 4 or 2
    constexpr int LDA = 40;              // padded row (elements)

    __shared__ __align__(16) __nv_bfloat16 As[2][128][LDA];
    __shared__ __align__(16) __nv_bfloat16 Bs[2][NT][LDA];

    const int tid  = threadIdx.x;
    const int lane = tid & 31;
    const int w    = tid >> 5;
    const int wm   = w >> 2;             // 0..1
    const int wn   = w & 3;              // 0..3
    const int m0   = blockIdx.x * 128;
    const int n0   = blockIdx.y * NT;

    const uint32_t sAs = smem_to_u32(&As[0][0][0]);
    const uint32_t sBs = smem_to_u32(&Bs[0][0][0]);
    constexpr uint32_t ASZ = 128*LDA*2;
    constexpr uint32_t BSZ = NT*LDA*2;

    float acc[4][NF][4];
#pragma unroll
    for (int i = 0; i < 4; i++)
#pragma unroll
        for (int j = 0; j < NF; j++)
#pragma unroll
            for (int e = 0; e < 4; e++) acc[i][j][e] = 0.f;

    const int KCn = K >> 5;              // 32-chunks per segment
    const int NIT = 3 * KCn;

    // chunk loader
    auto load_chunk = [&](int it, int buf) {
        const __nv_bfloat16 *Aseg, *Bseg; int kk;
        if (it < KCn)            { Aseg = Ah; Bseg = Bh; kk = it; }
        else if (it < 2*KCn)     { Aseg = Al; Bseg = Bh; kk = it - KCn; }
        else                     { Aseg = Ah; Bseg = Bl; kk = it - 2*KCn; }
        const int k0 = kk << 5;
        // A tile: 128 x 32 bf16 = 512 x 16B
#pragma unroll
        for (int q = 0; q < 2; ++q) {
            int c = tid + q*256;
            int row = c >> 2, sg = c & 3;
            cp16(sAs + buf*ASZ + (uint32_t)(row*LDA + sg*8)*2,
                 Aseg + (size_t)(m0+row)*K + k0 + sg*8);
        }
        // B tile: NT x 32 bf16
#pragma unroll
        for (int q = 0; q < NT/64; ++q) {
            int c = tid + q*256;
            int row = c >> 2, sg = c & 3;
            cp16(sBs + buf*BSZ + (uint32_t)(row*LDA + sg*8)*2,
                 Bseg + (size_t)(n0+row)*K + k0 + sg*8);
        }
        CP_COMMIT();
    };

    load_chunk(0, 0);

#pragma unroll 1
    for (int it = 0; it < NIT; ++it) {
        const int buf = it & 1;
        if (it + 1 < NIT) {
            load_chunk(it + 1, (it + 1) & 1);
            CP_WAIT(1);
        } else {
            CP_WAIT(0);
        }
        __syncthreads();

#pragma unroll
        for (int ks = 0; ks < 2; ++ks) {
            uint32_t a[4][4];
#pragma unroll
            for (int mf = 0; mf < 4; ++mf) {
                uint32_t addr = sAs + buf*ASZ +
                    (uint32_t)((wm*64 + mf*16 + (lane & 15))*LDA + ks*16 + ((lane >> 4) << 3))*2;
                LDSM_X4(a[mf], addr);
            }
            uint32_t b[NF][2];
#pragma unroll
            for (int nf2 = 0; nf2 < NF/2; ++nf2) {
                uint32_t r[4];
                uint32_t addr = sBs + buf*BSZ +
                    (uint32_t)((wn*NTW + nf2*16 + ((lane >> 4) << 3) + (lane & 7))*LDA
                               + ks*16 + (((lane >> 3) & 1) << 3))*2;
                LDSM_X4(r, addr);
                b[2*nf2][0] = r[0]; b[2*nf2][1] = r[1];
                b[2*nf2+1][0] = r[2]; b[2*nf2+1][1] = r[3];
            }
#pragma unroll
            for (int mf = 0; mf < 4; ++mf)
#pragma unroll
                for (int nf = 0; nf < NF; ++nf)
                    MMA16816(acc[mf][nf], a[mf], b[nf][0], b[nf][1]);
        }
        __syncthreads();
    }

    // epilogue: d0:(r,c) d1:(r,c+1) d2:(r+8,c) d3:(r+8,c+1); r=lane>>2, c=(lane&3)*2
#pragma unroll
    for (int mf = 0; mf < 4; ++mf) {
        const int r0 = m0 + wm*64 + mf*16 + (lane >> 2);
#pragma unroll
        for (int nf = 0; nf < NF; ++nf) {
            const int c0 = n0 + wn*NTW + nf*8 + ((lane & 3) << 1);
#pragma unroll
            for (int half = 0; half < 2; ++half) {
                const int row = r0 + half*8;
                float v0 = acc[mf][nf][2*half + 0];
                float v1 = acc[mf][nf][2*half + 1];
                if (c0 < Nclip) {
                    float vb0 = v0 + (bias ? bias[c0] : 0.f);
                    if (WF32) Cf[(size_t)row*Nout + c0] = vb0;
                    if (WSPLIT) {
                        __nv_bfloat16 h, l; split_bf16(vb0, h, l);
                        Chi[(size_t)row*Nout + c0] = h;
                        Clo[(size_t)row*Nout + c0] = l;
                    }
                }
                if (c0 + 1 < Nclip) {
                    float vb1 = v1 + (bias ? bias[c0+1] : 0.f);
                    if (WF32) Cf[(size_t)row*Nout + c0 + 1] = vb1;
                    if (WSPLIT) {
                        __nv_bfloat16 h, l; split_bf16(vb1, h, l);
                        Chi[(size_t)row*Nout + c0 + 1] = h;
                        Clo[(size_t)row*Nout + c0 + 1] = l;
                    }
                }
            }
        }
    }
}

// ---------------- prep kernels ----------------
__global__ __launch_bounds__(256)
void wprep_kernel(const float* __restrict__ W, __nv_bfloat16* __restrict__ Wh,
                  __nv_bfloat16* __restrict__ Wl, int K, int N, int NP)
{
    int idx = blockIdx.x*256 + threadIdx.x;
    if (idx >= NP*K) return;
    int n = idx / K, k = idx % K;
    float v = (n < N) ? W[(size_t)k*N + n] : 0.f;
    __nv_bfloat16 h, l; split_bf16(v, h, l);
    Wh[idx] = h; Wl[idx] = l;
}

__global__ __launch_bounds__(256)
void mixprep_kernel(const float* __restrict__ x, const float* __restrict__ qk)
{
    int idx = blockIdx.x*256 + threadIdx.x;      // over T*512
    int col = idx & 511, t = idx >> 9;
    float v = (col < 256) ? x[(size_t)t*256 + col] : qk[(size_t)t*256 + col - 256];
    __nv_bfloat16 h, l; split_bf16(v, h, l);
    g_mixAh[idx] = h; g_mixAl[idx] = l;
}

// ---------------- A_log preprocessing ----------------
__global__ void aprep_kernel(const float* __restrict__ A_log)
{
    int d = threadIdx.x;
    if (d >= DI) return;
    float Av[DS];
#pragma unroll
    for (int s = 0; s < DS; s++) { Av[s] = -__expf(A_log[d*DS + s]); g_A[d*DS + s] = Av[s]; }
    int ok = 1;
#pragma unroll
    for (int s = 0; s < DS; s++) {
        float tgt = Av[0] * (float)(s+1);
        if (fabsf(Av[s] - tgt) > 1e-5f * fabsf(Av[s]) + 1e-7f) ok = 0;
    }
    g_Aflag[d] = ok;
}

// ---------------- depthwise conv (K=4, causal) + SiLU; writes fp32 + split bf16 ----------------
__global__ __launch_bounds__(256)
void conv_silu_kernel(const float* __restrict__ conv_w, const float* __restrict__ conv_b)
{
    int idx = blockIdx.x * 256 + threadIdx.x;   // over T*DI
    int d = idx & (DI-1);
    int t = idx >> 8;
    int l = t & (LL-1);
    float acc = conv_b[d];
#pragma unroll
    for (int k = 0; k < KCV; k++) {
        int lt = l - (KCV-1) + k;
        if (lt >= 0) acc += g_XZ[(size_t)(t - (KCV-1) + k)*(2*DI) + d] * conv_w[d*KCV + k];
    }
    float sig = 1.f / (1.f + __expf(-acc));
    float v = acc * sig;
    g_XC[idx] = v;
    __nv_bfloat16 h, lo; split_bf16(v, h, lo);
    g_XCh[idx] = h; g_XCl[idx] = lo;
}

// ---------------- dt = softplus(dbl[:, :8] @ W_dt + b_dt) ----------------
__global__ __launch_bounds__(256)
void dt_kernel(const float* __restrict__ W_dt, const float* __restrict__ b_dt)
{
    int idx = blockIdx.x * 256 + threadIdx.x;   // over T*DI
    int d = idx & (DI-1);
    int t = idx >> 8;
    float acc = b_dt[d];
    const float* dbl = g_DBL + (size_t)t*40;
#pragma unroll
    for (int r = 0; r < DR; r++) acc += dbl[r] * W_dt[r*DI + d];
    float sp = (acc > 20.f) ? acc : log1pf(__expf(acc));
    g_DT[idx] = sp;
}

// ---------------- scan pass 1 ----------------
__global__ __launch_bounds__(256)
void scan_pass1()
{
    __shared__ float sB[CH][DS];
    const int bc = blockIdx.x;
    const int b = bc / NC, c = bc % NC;
    const int d = threadIdx.x;
    const int tok0 = b*LL + c*CH;

#pragma unroll
    for (int q = 0; q < (CH*DS)/256; q++) {
        int e = threadIdx.x + q*256;
        int j = e % DS, st = e / DS;
        sB[st][j] = g_DBL[(size_t)(tok0+st)*40 + 8 + j];
    }
    __syncthreads();

    const float A0 = g_A[d*DS];
    const int fast = g_Aflag[d];
    float S = 0.f;

    if (fast) {
        unsigned long long h2[DS/2];
#pragma unroll
        for (int sp = 0; sp < DS/2; sp++) h2[sp] = 0ULL;
        for (int st = 0; st < CH; st++) {
            int idx = (tok0+st)*DI + d;
            float dt = g_DT[idx];
            float x  = g_XC[idx];
            S += dt;
            float e1 = __expf(dt * A0);
            float e2 = e1 * e1;
            unsigned long long p2  = pack2(e1, e2);
            unsigned long long e22 = pack2(e2, e2);
            float dtx = dt * x;
            unsigned long long dtx2 = pack2(dtx, dtx);
            const unsigned long long* Bp = reinterpret_cast<const unsigned long long*>(sB[st]);
#pragma unroll
            for (int sp = 0; sp < DS/2; sp++) {
                h2[sp] = fma2(p2, h2[sp], mul2(dtx2, Bp[sp]));
                p2 = mul2(p2, e22);
            }
        }
        float* He = g_Hend + ((size_t)bc*DI + d)*DS;
#pragma unroll
        for (int sp = 0; sp < DS/2; sp++) {
            float2 v = unpack2(h2[sp]);
            He[2*sp] = v.x; He[2*sp+1] = v.y;
        }
    } else {
        float Av[DS], h[DS];
#pragma unroll
        for (int s = 0; s < DS; s++) { Av[s] = g_A[d*DS + s]; h[s] = 0.f; }
        for (int st = 0; st < CH; st++) {
            int idx = (tok0+st)*DI + d;
            float dt = g_DT[idx];
            float x  = g_XC[idx];
            S += dt;
            float dtx = dt * x;
#pragma unroll
            for (int s = 0; s < DS; s++) {
                float a = __expf(dt * Av[s]);
                h[s] = a*h[s] + dtx * sB[st][s];
            }
        }
        float* He = g_Hend + ((size_t)bc*DI + d)*DS;
#pragma unroll
        for (int s = 0; s < DS; s++) He[s] = h[s];
    }
    g_S[(size_t)bc*DI + d] = S;
}

// ---------------- inter-chunk combine ----------------
__global__ __launch_bounds__(256)
void scan_combine()
{
    int g = blockIdx.x * 256 + threadIdx.x;
    int s = g & (DS-1);
    int d = (g >> 4) & (DI-1);
    int b = g >> 12;
    float Av = g_A[d*DS + s];
    float h = 0.f;
    for (int c = 0; c < NC; c++) {
        size_t base = ((size_t)(b*NC + c)*DI + d)*DS + s;
        g_Hin[base] = h;
        float S = g_S[(size_t)(b*NC + c)*DI + d];
        h = __expf(Av * S) * h + g_Hend[base];
    }
}

// ---------------- scan pass 2: emit y=(scan + xc*D)*silu(z) as split bf16 ----------------
__global__ __launch_bounds__(256)
void scan_pass2(const float* __restrict__ D_param)
{
    __shared__ float sBC[CH][2*DS];
    const int bc = blockIdx.x;
    const int b = bc / NC, c = bc % NC;
    const int d = threadIdx.x;
    const int tok0 = b*LL + c*CH;

#pragma unroll
    for (int q = 0; q < (CH*2*DS)/256; q++) {
        int e = threadIdx.x + q*256;
        int j = e & (2*DS - 1), st = e >> 5;
        sBC[st][j] = g_DBL[(size_t)(tok0+st)*40 + 8 + j];
    }
    __syncthreads();

    const float A0 = g_A[d*DS];
    const int fast = g_Aflag[d];
    const float Dp = D_param[d];
    const size_t hbase = ((size_t)bc*DI + d)*DS;

    if (fast) {
        unsigned long long h2[DS/2];
#pragma unroll
        for (int sp = 0; sp < DS/2; sp++)
            h2[sp] = pack2(g_Hin[hbase + 2*sp], g_Hin[hbase + 2*sp + 1]);
        for (int st = 0; st < CH; st++) {
            int idx = (tok0+st)*DI + d;
            float dt = g_DT[idx];
            float x  = g_XC[idx];
            float e1 = __expf(dt * A0);
            float e2 = e1 * e1;
            unsigned long long p2  = pack2(e1, e2);
            unsigned long long e22 = pack2(e2, e2);
            float dtx = dt * x;
            unsigned long long dtx2 = pack2(dtx, dtx);
            const unsigned long long* BCp = reinterpret_cast<const unsigned long long*>(sBC[st]);
            unsigned long long y2 = 0ULL;
#pragma unroll
            for (int sp = 0; sp < DS/2; sp++) {
                h2[sp] = fma2(p2, h2[sp], mul2(dtx2, BCp[sp]));
                y2 = fma2(h2[sp], BCp[DS/2 + sp], y2);
                p2 = mul2(p2, e22);
            }
            float2 yv = unpack2(y2);
            float y = yv.x + yv.y;
            float z = g_XZ[(size_t)(tok0+st)*(2*DI) + DI + d];
            float sz = z / (1.f + __expf(-z));
            float yo = (y + x*Dp) * sz;
            __nv_bfloat16 h, lo; split_bf16(yo, h, lo);
            g_Yh[idx] = h; g_Yl[idx] = lo;
        }
    } else {
        float Av[DS], h[DS];
#pragma unroll
        for (int s = 0; s < DS; s++) { Av[s] = g_A[d*DS + s]; h[s] = g_Hin[hbase + s]; }
        for (int st = 0; st < CH; st++) {
            int idx = (tok0+st)*DI + d;
            float dt = g_DT[idx];
            float x  = g_XC[idx];
            float dtx = dt * x;
            float y = 0.f;
#pragma unroll
            for (int s = 0; s < DS; s++) {
                float a = __expf(dt * Av[s]);
                h[s] = a*h[s] + dtx * sBC[st][s];
                y += h[s] * sBC[st][DS + s];
            }
            float z = g_XZ[(size_t)(tok0+st)*(2*DI) + DI + d];
            float sz = z / (1.f + __expf(-z));
            float yo = (y + x*Dp) * sz;
            __nv_bfloat16 hh, lo; split_bf16(yo, hh, lo);
            g_Yh[idx] = hh; g_Yl[idx] = lo;
        }
    }
}

// ---------------- host launch ----------------
extern "C" void kernel_launch(void* const* d_in, const int* in_sizes, int n_in,
                              void* d_out, int out_size)
{
    const float* x      = (const float*)d_in[0];
    const float* qk     = (const float*)d_in[1];
    const float* W_mix  = (const float*)d_in[2];
    const float* b_mix  = (const float*)d_in[3];
    const float* W_in   = (const float*)d_in[4];
    const float* b_in   = (const float*)d_in[5];
    const float* conv_w = (const float*)d_in[6];
    const float* conv_b = (const float*)d_in[7];
    const float* W_xproj= (const float*)d_in[8];
    const float* W_dt   = (const float*)d_in[9];
    const float* b_dt   = (const float*)d_in[10];
    const float* A_log  = (const float*)d_in[11];
    const float* D_param= (const float*)d_in[12];
    const float* W_op   = (const float*)d_in[13];
    const float* b_op   = (const float*)d_in[14];
    const float* W_out  = (const float*)d_in[15];
    const float* b_out  = (const float*)d_in[16];
    float* out = (float*)d_out;

    // symbol addresses
    __nv_bfloat16 *pMixAh,*pMixAl,*pHh,*pHl,*pXCh,*pXCl,*pYh,*pYl,*pO1h,*pO1l;
    __nv_bfloat16 *pWmixh,*pWmixl,*pWinh,*pWinl,*pWxph,*pWxpl,*pWoph,*pWopl,*pWouth,*pWoutl;
    float *pXZ,*pDBL;
    cudaGetSymbolAddress((void**)&pMixAh, g_mixAh); cudaGetSymbolAddress((void**)&pMixAl, g_mixAl);
    cudaGetSymbolAddress((void**)&pHh, g_Hh);       cudaGetSymbolAddress((void**)&pHl, g_Hl);
    cudaGetSymbolAddress((void**)&pXCh, g_XCh);     cudaGetSymbolAddress((void**)&pXCl, g_XCl);
    cudaGetSymbolAddress((void**)&pYh, g_Yh);       cudaGetSymbolAddress((void**)&pYl, g_Yl);
    cudaGetSymbolAddress((void**)&pO1h, g_O1h);     cudaGetSymbolAddress((void**)&pO1l, g_O1l);
    cudaGetSymbolAddress((void**)&pWmixh, g_Wmix_h);cudaGetSymbolAddress((void**)&pWmixl, g_Wmix_l);
    cudaGetSymbolAddress((void**)&pWinh, g_Win_h);  cudaGetSymbolAddress((void**)&pWinl, g_Win_l);
    cudaGetSymbolAddress((void**)&pWxph, g_Wxp_h);  cudaGetSymbolAddress((void**)&pWxpl, g_Wxp_l);
    cudaGetSymbolAddress((void**)&pWoph, g_Wop_h);  cudaGetSymbolAddress((void**)&pWopl, g_Wop_l);
    cudaGetSymbolAddress((void**)&pWouth, g_Wout_h);cudaGetSymbolAddress((void**)&pWoutl, g_Wout_l);
    cudaGetSymbolAddress((void**)&pXZ, g_XZ);       cudaGetSymbolAddress((void**)&pDBL, g_DBL);

    // 0) prep: A matrix, weights (transpose + bf16 split), mix input split
    aprep_kernel<<<1, 256>>>(A_log);
    wprep_kernel<<<(128*512+255)/256, 256>>>(W_mix,  pWmixh, pWmixl, 512, 128, 128);
    wprep_kernel<<<(512*128+255)/256, 256>>>(W_in,   pWinh,  pWinl,  128, 512, 512);
    wprep_kernel<<<(64*256+255)/256,  256>>>(W_xproj,pWxph,  pWxpl,  256, 40,  64);
    wprep_kernel<<<(128*256+255)/256, 256>>>(W_op,   pWoph,  pWopl,  256, 128, 128);
    wprep_kernel<<<(256*128+255)/256, 256>>>(W_out,  pWouth, pWoutl, 128, 256, 256);
    mixprep_kernel<<<(TT*512)/256, 256>>>(x, qk);

    // 1) H = [x|qk] @ W_mix + b_mix -> split bf16   (K=512, N=128)
    gemm_mma<128,false,true><<<dim3(TT/128, 1), 256>>>(
        pMixAh, pMixAl, pWmixh, pWmixl, b_mix, nullptr, pHh, pHl, 512, DM, DM);

    // 2) XZ = H @ W_in + b_in -> fp32               (K=128, N=512)
    gemm_mma<128,true,false><<<dim3(TT/128, 4), 256>>>(
        pHh, pHl, pWinh, pWinl, b_in, pXZ, nullptr, nullptr, 128, 2*DI, 2*DI);

    // 3) conv + silu -> XC fp32 + split
    conv_silu_kernel<<<(TT*DI)/256, 256>>>(conv_w, conv_b);

    // 4) DBL = XC @ W_xproj -> fp32 (cols<40)       (K=256, N=40 padded 64)
    gemm_mma<64,true,false><<<dim3(TT/128, 1), 256>>>(
        pXCh, pXCl, pWxph, pWxpl, nullptr, pDBL, nullptr, nullptr, 256, 40, 40);

    // 5) dt
    dt_kernel<<<(TT*DI)/256, 256>>>(W_dt, b_dt);

    // 6-8) chunked selective scan
    scan_pass1  <<<BB*NC, 256>>>();
    scan_combine<<<(BB*DI*DS)/256, 256>>>();
    scan_pass2  <<<BB*NC, 256>>>(D_param);

    // 9) O1 = Y @ W_op + b_op -> split bf16         (K=256, N=128)
    gemm_mma<128,false,true><<<dim3(TT/128, 1), 256>>>(
        pYh, pYl, pWoph, pWopl, b_op, nullptr, pO1h, pO1l, 256, DM, DM);

    // 10) out = O1 @ W_out + b_out -> fp32          (K=128, N=256)
    gemm_mma<128,true,false><<<dim3(TT/128, 2), 256>>>(
        pO1h, pO1l, pWouth, pWoutl, b_out, out, nullptr, nullptr, 128, CC, CC);
}

// round 13
// speedup vs baseline: 1.7408x; 1.3076x over previous
#include <cuda_runtime.h>
#include <cuda_bf16.h>
#include <cstdint>

// ---------------- problem constants ----------------
#define BB 16
#define LL 4096
#define CC 256
#define DM 128            // d_model
#define DI 256            // d_inner
#define DS 16             // d_state
#define DR 8              // dt_rank
#define KCV 4             // conv kernel
#define TT (BB*LL)        // 65536 tokens
#define CH 128            // scan chunk length
#define NC (LL/CH)        // 32 chunks per batch

// ---------------- scratch (device globals; no allocation allowed) ----------------
__device__ __align__(16) float g_H  [(size_t)TT*DM];        // mix output (fp32)
__device__ __align__(16) float g_XZ [(size_t)TT*(2*DI)];    // in-proj output (xc_raw | z)
__device__ __align__(16) float g_XC [(size_t)TT*DI];        // conv+silu output
__device__ __align__(16) float g_DBL[(size_t)TT*40];        // xproj output
__device__ __align__(16) float g_DT [(size_t)TT*DI];        // softplus dt
__device__ __align__(16) float g_Y  [(size_t)TT*DI];        // scan output (fp32)
__device__ __align__(16) float g_O1 [(size_t)TT*DM];        // op output (fp32)
// transposed + split weights: Wt[n,k] = W[k,n]
__device__ __align__(16) __nv_bfloat16 g_Wmix_h[DM*512],  g_Wmix_l[DM*512];
__device__ __align__(16) __nv_bfloat16 g_Win_h [512*DM],  g_Win_l [512*DM];
__device__ __align__(16) __nv_bfloat16 g_Wxp_h [64*DI],   g_Wxp_l [64*DI];
__device__ __align__(16) __nv_bfloat16 g_Wop_h [DM*DI],   g_Wop_l [DM*DI];
__device__ __align__(16) __nv_bfloat16 g_Wout_h[CC*DM],   g_Wout_l[CC*DM];
// scan scratch
__device__ float g_Hend[(size_t)BB*NC*DI*DS];
__device__ float g_Hin [(size_t)BB*NC*DI*DS];
__device__ float g_S   [(size_t)BB*NC*DI];
__device__ float g_A   [DI*DS];
__device__ int   g_Aflag[DI];

// ---------------- PTX helpers (sm_80-compatible; no 'a'-suffix features) ----------------
__device__ __forceinline__ uint32_t smem_to_u32(const void* p) {
    uint32_t a;
    asm("{ .reg .u64 t; cvta.to.shared.u64 t, %1; cvt.u32.u64 %0, t; }" : "=r"(a) : "l"(p));
    return a;
}
__device__ __forceinline__ void cp16(uint32_t s, const void* g) {
    asm volatile("cp.async.cg.shared.global [%0], [%1], 16;" :: "r"(s), "l"(g));
}
#define CP_COMMIT() asm volatile("cp.async.commit_group;" ::: "memory")
#define CP_WAIT(n)  asm volatile("cp.async.wait_group %0;" :: "n"(n) : "memory")

#define LDSM_X4(r, addr) \
    asm volatile("ldmatrix.sync.aligned.m8n8.x4.shared.b16 {%0,%1,%2,%3}, [%4];" \
        : "=r"((r)[0]), "=r"((r)[1]), "=r"((r)[2]), "=r"((r)[3]) : "r"(addr))

#define MMA16816(d, a, b0, b1) \
    asm volatile("mma.sync.aligned.m16n8k16.row.col.f32.bf16.bf16.f32 " \
        "{%0,%1,%2,%3}, {%4,%5,%6,%7}, {%8,%9}, {%0,%1,%2,%3};" \
        : "+f"((d)[0]), "+f"((d)[1]), "+f"((d)[2]), "+f"((d)[3]) \
        : "r"((a)[0]), "r"((a)[1]), "r"((a)[2]), "r"((a)[3]), "r"(b0), "r"(b1))

// ---------------- packed f32x2 helpers (scan) ----------------
__device__ __forceinline__ unsigned long long pack2(float lo, float hi){
    unsigned long long r; asm("mov.b64 %0,{%1,%2};" : "=l"(r) : "f"(lo), "f"(hi)); return r;
}
__device__ __forceinline__ float2 unpack2(unsigned long long v){
    float2 r; asm("mov.b64 {%0,%1},%2;" : "=f"(r.x), "=f"(r.y) : "l"(v)); return r;
}
__device__ __forceinline__ unsigned long long mul2(unsigned long long a, unsigned long long b){
    unsigned long long d; asm("mul.rn.f32x2 %0,%1,%2;" : "=l"(d) : "l"(a), "l"(b)); return d;
}
__device__ __forceinline__ unsigned long long fma2(unsigned long long a, unsigned long long b, unsigned long long c){
    unsigned long long d; asm("fma.rn.f32x2 %0,%1,%2,%3;" : "=l"(d) : "l"(a), "l"(b), "l"(c)); return d;
}

__device__ __forceinline__ void split_bf16(float v, __nv_bfloat16& h, __nv_bfloat16& l) {
    h = __float2bfloat16(v);
    l = __float2bfloat16(v - __bfloat162float(h));
}
__device__ __forceinline__ uint32_t pack_bf(__nv_bfloat16 a, __nv_bfloat16 b) {
    uint16_t ua = *reinterpret_cast<uint16_t*>(&a);
    uint16_t ub = *reinterpret_cast<uint16_t*>(&b);
    return (uint32_t)ua | ((uint32_t)ub << 16);
}

// =====================================================================
// mma.sync split GEMM, fp32 A in global: C[m,n] = sum_k A[m,k]*Wt[n,k] + bias
// Per K=32 chunk: load A fp32 ONCE (register-staged), split to Ah/Al smem;
// cp.async pre-split weight tiles Bh/Bl; issue 3 segment MMA passes
// (Ah*Bh + Ah*Bl + Al*Bh) from one smem residency. fp32 accumulate.
// CTA: 128 x NT tile, 8 warps (2x4), warp tile 64 x NT/4, double-buffered.
// =====================================================================
template<int NT, bool CONCAT>
__global__ __launch_bounds__(256)
void gemm_mma(const float* __restrict__ A0, const float* __restrict__ A1,
              const __nv_bfloat16* __restrict__ Bh, const __nv_bfloat16* __restrict__ Bl,
              const float* __restrict__ bias, float* __restrict__ Cf,
              int K, int Nout, int Nclip)
{
    constexpr int NTW = NT / 4;          // warp n-tile: 32 or 16
    constexpr int NF  = NTW / 8;         // n-frags per warp: 4 or 2
    constexpr int LDA = 40;              // padded row (elements)
    constexpr uint32_t ABUF = 128*LDA*2; // bytes per A buffer
    constexpr uint32_t BBUF = NT*LDA*2;  // bytes per B buffer

    extern __shared__ char dsm[];
    const uint32_t sAh = smem_to_u32(dsm);
    const uint32_t sAl = sAh + 2*ABUF;
    const uint32_t sBh = sAl + 2*ABUF;
    const uint32_t sBl = sBh + 2*BBUF;

    const int tid  = threadIdx.x;
    const int lane = tid & 31;
    const int w    = tid >> 5;
    const int wm   = w >> 2;
    const int wn   = w & 3;
    const int m0   = blockIdx.x * 128;
    const int n0   = blockIdx.y * NT;

    float acc[4][NF][4];
#pragma unroll
    for (int i = 0; i < 4; i++)
#pragma unroll
        for (int j = 0; j < NF; j++)
#pragma unroll
            for (int e = 0; e < 4; e++) acc[i][j][e] = 0.f;

    const int NCH = K >> 5;              // K=32 chunks
    float4 av[4];                        // register-staged A chunk (16 fp32/thread)

    // ---- loaders ----
    auto ldg_A = [&](int kk) {
        const int k0 = kk << 5;
#pragma unroll
        for (int q = 0; q < 4; ++q) {
            int c = tid + q*256;
            int row = c >> 3, sg = c & 7;
            int gk = k0 + sg*4;
            const float* src;
            if (CONCAT) src = (gk < 256) ? A0 + (size_t)(m0+row)*256 + gk
                                         : A1 + (size_t)(m0+row)*256 + (gk-256);
            else        src = A0 + (size_t)(m0+row)*K + gk;
            av[q] = *reinterpret_cast<const float4*>(src);
        }
    };
    auto sts_A = [&](int buf) {
#pragma unroll
        for (int q = 0; q < 4; ++q) {
            int c = tid + q*256;
            int row = c >> 3, sg = c & 7;
            __nv_bfloat16 h0,l0,h1,l1,h2,l2,h3,l3;
            split_bf16(av[q].x, h0, l0); split_bf16(av[q].y, h1, l1);
            split_bf16(av[q].z, h2, l2); split_bf16(av[q].w, h3, l3);
            uint32_t off = (uint32_t)(row*LDA + sg*4)*2;
            uint2 hv = { pack_bf(h0,h1), pack_bf(h2,h3) };
            uint2 lv = { pack_bf(l0,l1), pack_bf(l2,l3) };
            *reinterpret_cast<uint2*>(dsm + buf*ABUF + off) = hv;
            *reinterpret_cast<uint2*>(dsm + 2*ABUF + buf*ABUF + off) = lv;
        }
    };
    auto cpa_B = [&](int kk, int buf) {
        const int k0 = kk << 5;
#pragma unroll
        for (int q = 0; q < NT/64; ++q) {
            int c = tid + q*256;
            int row = c >> 2, sg = c & 3;
            cp16(sBh + buf*BBUF + (uint32_t)(row*LDA + sg*8)*2,
                 Bh + (size_t)(n0+row)*K + k0 + sg*8);
        }
#pragma unroll
        for (int q = 0; q < NT/64; ++q) {
            int c = tid + q*256;
            int row = c >> 2, sg = c & 3;
            cp16(sBl + buf*BBUF + (uint32_t)(row*LDA + sg*8)*2,
                 Bl + (size_t)(n0+row)*K + k0 + sg*8);
        }
        CP_COMMIT();
    };

    // ---- prologue: chunk 0 into buf 0 ----
    ldg_A(0);
    cpa_B(0, 0);
    sts_A(0);
    CP_WAIT(0);
    __syncthreads();

    int buf = 0;
#pragma unroll 1
    for (int it = 0; it < NCH; ++it) {
        const bool more = (it + 1 < NCH);
        if (more) { ldg_A(it + 1); cpa_B(it + 1, buf ^ 1); }

        // ---- compute: 3 segments from this chunk ----
#pragma unroll
        for (int ks = 0; ks < 2; ++ks) {
            uint32_t a[4][4];
            uint32_t bh[NF][2], bl[NF][2];
#pragma unroll
            for (int mf = 0; mf < 4; ++mf) {
                uint32_t addr = sAh + buf*ABUF +
                    (uint32_t)((wm*64 + mf*16 + (lane & 15))*LDA + ks*16 + ((lane >> 4) << 3))*2;
                LDSM_X4(a[mf], addr);
            }
#pragma unroll
            for (int nf2 = 0; nf2 < NF/2; ++nf2) {
                uint32_t r[4];
                uint32_t addr = sBh + buf*BBUF +
                    (uint32_t)((wn*NTW + nf2*16 + ((lane >> 4) << 3) + (lane & 7))*LDA
                               + ks*16 + (((lane >> 3) & 1) << 3))*2;
                LDSM_X4(r, addr);
                bh[2*nf2][0] = r[0]; bh[2*nf2][1] = r[1];
                bh[2*nf2+1][0] = r[2]; bh[2*nf2+1][1] = r[3];
            }
#pragma unroll
            for (int nf2 = 0; nf2 < NF/2; ++nf2) {
                uint32_t r[4];
                uint32_t addr = sBl + buf*BBUF +
                    (uint32_t)((wn*NTW + nf2*16 + ((lane >> 4) << 3) + (lane & 7))*LDA
                               + ks*16 + (((lane >> 3) & 1) << 3))*2;
                LDSM_X4(r, addr);
                bl[2*nf2][0] = r[0]; bl[2*nf2][1] = r[1];
                bl[2*nf2+1][0] = r[2]; bl[2*nf2+1][1] = r[3];
            }
            // seg0: Ah*Bh ; seg1: Ah*Bl
#pragma unroll
            for (int mf = 0; mf < 4; ++mf)
#pragma unroll
                for (int nf = 0; nf < NF; ++nf) {
                    MMA16816(acc[mf][nf], a[mf], bh[nf][0], bh[nf][1]);
                    MMA16816(acc[mf][nf], a[mf], bl[nf][0], bl[nf][1]);
                }
            // seg2: Al*Bh (reload a from Al)
#pragma unroll
            for (int mf = 0; mf < 4; ++mf) {
                uint32_t addr = sAl + buf*ABUF +
                    (uint32_t)((wm*64 + mf*16 + (lane & 15))*LDA + ks*16 + ((lane >> 4) << 3))*2;
                LDSM_X4(a[mf], addr);
            }
#pragma unroll
            for (int mf = 0; mf < 4; ++mf)
#pragma unroll
                for (int nf = 0; nf < NF; ++nf)
                    MMA16816(acc[mf][nf], a[mf], bh[nf][0], bh[nf][1]);
        }

        if (more) {
            sts_A(buf ^ 1);
            CP_WAIT(0);
            __syncthreads();
            buf ^= 1;
        }
    }

    // ---- epilogue (fp32 + bias) ----
#pragma unroll
    for (int mf = 0; mf < 4; ++mf) {
        const int r0 = m0 + wm*64 + mf*16 + (lane >> 2);
#pragma unroll
        for (int nf = 0; nf < NF; ++nf) {
            const int c0 = n0 + wn*NTW + nf*8 + ((lane & 3) << 1);
#pragma unroll
            for (int half = 0; half < 2; ++half) {
                const int row = r0 + half*8;
                if (c0 < Nclip)
                    Cf[(size_t)row*Nout + c0]     = acc[mf][nf][2*half]   + (bias ? bias[c0]   : 0.f);
                if (c0 + 1 < Nclip)
                    Cf[(size_t)row*Nout + c0 + 1] = acc[mf][nf][2*half+1] + (bias ? bias[c0+1] : 0.f);
            }
        }
    }
}

// ---------------- prep kernels ----------------
__global__ __launch_bounds__(256)
void wprep_kernel(const float* __restrict__ W, __nv_bfloat16* __restrict__ Wh,
                  __nv_bfloat16* __restrict__ Wl, int K, int N, int NP)
{
    int idx = blockIdx.x*256 + threadIdx.x;
    if (idx >= NP*K) return;
    int n = idx / K, k = idx % K;
    float v = (n < N) ? W[(size_t)k*N + n] : 0.f;
    __nv_bfloat16 h, l; split_bf16(v, h, l);
    Wh[idx] = h; Wl[idx] = l;
}

// ---------------- A_log preprocessing ----------------
__global__ void aprep_kernel(const float* __restrict__ A_log)
{
    int d = threadIdx.x;
    if (d >= DI) return;
    float Av[DS];
#pragma unroll
    for (int s = 0; s < DS; s++) { Av[s] = -__expf(A_log[d*DS + s]); g_A[d*DS + s] = Av[s]; }
    int ok = 1;
#pragma unroll
    for (int s = 0; s < DS; s++) {
        float tgt = Av[0] * (float)(s+1);
        if (fabsf(Av[s] - tgt) > 1e-5f * fabsf(Av[s]) + 1e-7f) ok = 0;
    }
    g_Aflag[d] = ok;
}

// ---------------- depthwise conv (K=4, causal) + SiLU ----------------
__global__ __launch_bounds__(256)
void conv_silu_kernel(const float* __restrict__ conv_w, const float* __restrict__ conv_b)
{
    int idx = blockIdx.x * 256 + threadIdx.x;   // over T*DI
    int d = idx & (DI-1);
    int t = idx >> 8;
    int l = t & (LL-1);
    float acc = conv_b[d];
#pragma unroll
    for (int k = 0; k < KCV; k++) {
        int lt = l - (KCV-1) + k;
        if (lt >= 0) acc += g_XZ[(size_t)(t - (KCV-1) + k)*(2*DI) + d] * conv_w[d*KCV + k];
    }
    float sig = 1.f / (1.f + __expf(-acc));
    g_XC[idx] = acc * sig;
}

// ---------------- dt = softplus(dbl[:, :8] @ W_dt + b_dt) ----------------
__global__ __launch_bounds__(256)
void dt_kernel(const float* __restrict__ W_dt, const float* __restrict__ b_dt)
{
    int idx = blockIdx.x * 256 + threadIdx.x;   // over T*DI
    int d = idx & (DI-1);
    int t = idx >> 8;
    float acc = b_dt[d];
    const float* dbl = g_DBL + (size_t)t*40;
#pragma unroll
    for (int r = 0; r < DR; r++) acc += dbl[r] * W_dt[r*DI + d];
    float sp = (acc > 20.f) ? acc : log1pf(__expf(acc));
    g_DT[idx] = sp;
}

// ---------------- scan pass 1 ----------------
__global__ __launch_bounds__(256)
void scan_pass1()
{
    __shared__ float sB[CH][DS];
    const int bc = blockIdx.x;
    const int b = bc / NC, c = bc % NC;
    const int d = threadIdx.x;
    const int tok0 = b*LL + c*CH;

#pragma unroll
    for (int q = 0; q < (CH*DS)/256; q++) {
        int e = threadIdx.x + q*256;
        int j = e % DS, st = e / DS;
        sB[st][j] = g_DBL[(size_t)(tok0+st)*40 + 8 + j];
    }
    __syncthreads();

    const float A0 = g_A[d*DS];
    const int fast = g_Aflag[d];
    float S = 0.f;

    if (fast) {
        unsigned long long h2[DS/2];
#pragma unroll
        for (int sp = 0; sp < DS/2; sp++) h2[sp] = 0ULL;
        for (int st = 0; st < CH; st++) {
            int idx = (tok0+st)*DI + d;
            float dt = g_DT[idx];
            float x  = g_XC[idx];
            S += dt;
            float e1 = __expf(dt * A0);
            float e2 = e1 * e1;
            unsigned long long p2  = pack2(e1, e2);
            unsigned long long e22 = pack2(e2, e2);
            float dtx = dt * x;
            unsigned long long dtx2 = pack2(dtx, dtx);
            const unsigned long long* Bp = reinterpret_cast<const unsigned long long*>(sB[st]);
#pragma unroll
            for (int sp = 0; sp < DS/2; sp++) {
                h2[sp] = fma2(p2, h2[sp], mul2(dtx2, Bp[sp]));
                p2 = mul2(p2, e22);
            }
        }
        float* He = g_Hend + ((size_t)bc*DI + d)*DS;
#pragma unroll
        for (int sp = 0; sp < DS/2; sp++) {
            float2 v = unpack2(h2[sp]);
            He[2*sp] = v.x; He[2*sp+1] = v.y;
        }
    } else {
        float Av[DS], h[DS];
#pragma unroll
        for (int s = 0; s < DS; s++) { Av[s] = g_A[d*DS + s]; h[s] = 0.f; }
        for (int st = 0; st < CH; st++) {
            int idx = (tok0+st)*DI + d;
            float dt = g_DT[idx];
            float x  = g_XC[idx];
            S += dt;
            float dtx = dt * x;
#pragma unroll
            for (int s = 0; s < DS; s++) {
                float a = __expf(dt * Av[s]);
                h[s] = a*h[s] + dtx * sB[st][s];
            }
        }
        float* He = g_Hend + ((size_t)bc*DI + d)*DS;
#pragma unroll
        for (int s = 0; s < DS; s++) He[s] = h[s];
    }
    g_S[(size_t)bc*DI + d] = S;
}

// ---------------- inter-chunk combine ----------------
__global__ __launch_bounds__(256)
void scan_combine()
{
    int g = blockIdx.x * 256 + threadIdx.x;
    int s = g & (DS-1);
    int d = (g >> 4) & (DI-1);
    int b = g >> 12;
    float Av = g_A[d*DS + s];
    float h = 0.f;
    for (int c = 0; c < NC; c++) {
        size_t base = ((size_t)(b*NC + c)*DI + d)*DS + s;
        g_Hin[base] = h;
        float S = g_S[(size_t)(b*NC + c)*DI + d];
        h = __expf(Av * S) * h + g_Hend[base];
    }
}

// ---------------- scan pass 2: emit y=(scan + xc*D)*silu(z), fp32 ----------------
__global__ __launch_bounds__(256)
void scan_pass2(const float* __restrict__ D_param)
{
    __shared__ float sBC[CH][2*DS];
    const int bc = blockIdx.x;
    const int b = bc / NC, c = bc % NC;
    const int d = threadIdx.x;
    const int tok0 = b*LL + c*CH;

#pragma unroll
    for (int q = 0; q < (CH*2*DS)/256; q++) {
        int e = threadIdx.x + q*256;
        int j = e & (2*DS - 1), st = e >> 5;
        sBC[st][j] = g_DBL[(size_t)(tok0+st)*40 + 8 + j];
    }
    __syncthreads();

    const float A0 = g_A[d*DS];
    const int fast = g_Aflag[d];
    const float Dp = D_param[d];
    const size_t hbase = ((size_t)bc*DI + d)*DS;

    if (fast) {
        unsigned long long h2[DS/2];
#pragma unroll
        for (int sp = 0; sp < DS/2; sp++)
            h2[sp] = pack2(g_Hin[hbase + 2*sp], g_Hin[hbase + 2*sp + 1]);
        for (int st = 0; st < CH; st++) {
            int idx = (tok0+st)*DI + d;
            float dt = g_DT[idx];
            float x  = g_XC[idx];
            float e1 = __expf(dt * A0);
            float e2 = e1 * e1;
            unsigned long long p2  = pack2(e1, e2);
            unsigned long long e22 = pack2(e2, e2);
            float dtx = dt * x;
            unsigned long long dtx2 = pack2(dtx, dtx);
            const unsigned long long* BCp = reinterpret_cast<const unsigned long long*>(sBC[st]);
            unsigned long long y2 = 0ULL;
#pragma unroll
            for (int sp = 0; sp < DS/2; sp++) {
                h2[sp] = fma2(p2, h2[sp], mul2(dtx2, BCp[sp]));
                y2 = fma2(h2[sp], BCp[DS/2 + sp], y2);
                p2 = mul2(p2, e22);
            }
            float2 yv = unpack2(y2);
            float y = yv.x + yv.y;
            float z = g_XZ[(size_t)(tok0+st)*(2*DI) + DI + d];
            float sz = z / (1.f + __expf(-z));
            g_Y[idx] = (y + x*Dp) * sz;
        }
    } else {
        float Av[DS], h[DS];
#pragma unroll
        for (int s = 0; s < DS; s++) { Av[s] = g_A[d*DS + s]; h[s] = g_Hin[hbase + s]; }
        for (int st = 0; st < CH; st++) {
            int idx = (tok0+st)*DI + d;
            float dt = g_DT[idx];
            float x  = g_XC[idx];
            float dtx = dt * x;
            float y = 0.f;
#pragma unroll
            for (int s = 0; s < DS; s++) {
                float a = __expf(dt * Av[s]);
                h[s] = a*h[s] + dtx * sBC[st][s];
                y += h[s] * sBC[st][DS + s];
            }
            float z = g_XZ[(size_t)(tok0+st)*(2*DI) + DI + d];
            float sz = z / (1.f + __expf(-z));
            g_Y[idx] = (y + x*Dp) * sz;
        }
    }
}

// ---------------- host launch ----------------
extern "C" void kernel_launch(void* const* d_in, const int* in_sizes, int n_in,
                              void* d_out, int out_size)
{
    const float* x      = (const float*)d_in[0];
    const float* qk     = (const float*)d_in[1];
    const float* W_mix  = (const float*)d_in[2];
    const float* b_mix  = (const float*)d_in[3];
    const float* W_in   = (const float*)d_in[4];
    const float* b_in   = (const float*)d_in[5];
    const float* conv_w = (const float*)d_in[6];
    const float* conv_b = (const float*)d_in[7];
    const float* W_xproj= (const float*)d_in[8];
    const float* W_dt   = (const float*)d_in[9];
    const float* b_dt   = (const float*)d_in[10];
    const float* A_log  = (const float*)d_in[11];
    const float* D_param= (const float*)d_in[12];
    const float* W_op   = (const float*)d_in[13];
    const float* b_op   = (const float*)d_in[14];
    const float* W_out  = (const float*)d_in[15];
    const float* b_out  = (const float*)d_in[16];
    float* out = (float*)d_out;

    // symbol addresses
    float *pH,*pXZ,*pXC,*pDBL,*pY,*pO1;
    __nv_bfloat16 *pWmixh,*pWmixl,*pWinh,*pWinl,*pWxph,*pWxpl,*pWoph,*pWopl,*pWouth,*pWoutl;
    cudaGetSymbolAddress((void**)&pH,  g_H);
    cudaGetSymbolAddress((void**)&pXZ, g_XZ);
    cudaGetSymbolAddress((void**)&pXC, g_XC);
    cudaGetSymbolAddress((void**)&pDBL,g_DBL);
    cudaGetSymbolAddress((void**)&pY,  g_Y);
    cudaGetSymbolAddress((void**)&pO1, g_O1);
    cudaGetSymbolAddress((void**)&pWmixh, g_Wmix_h);cudaGetSymbolAddress((void**)&pWmixl, g_Wmix_l);
    cudaGetSymbolAddress((void**)&pWinh, g_Win_h);  cudaGetSymbolAddress((void**)&pWinl, g_Win_l);
    cudaGetSymbolAddress((void**)&pWxph, g_Wxp_h);  cudaGetSymbolAddress((void**)&pWxpl, g_Wxp_l);
    cudaGetSymbolAddress((void**)&pWoph, g_Wop_h);  cudaGetSymbolAddress((void**)&pWopl, g_Wop_l);
    cudaGetSymbolAddress((void**)&pWouth, g_Wout_h);cudaGetSymbolAddress((void**)&pWoutl, g_Wout_l);

    constexpr int SM128 = 2*(128*40*2)*2 + 2*(128*40*2)*2;   // Ah,Al,Bh,Bl double-buffered: 81920
    constexpr int SM64  = 2*(128*40*2)*2 + 2*(64*40*2)*2;    // 61440
    cudaFuncSetAttribute(gemm_mma<128,true>,  cudaFuncAttributeMaxDynamicSharedMemorySize, SM128);
    cudaFuncSetAttribute(gemm_mma<128,false>, cudaFuncAttributeMaxDynamicSharedMemorySize, SM128);
    cudaFuncSetAttribute(gemm_mma<64,false>,  cudaFuncAttributeMaxDynamicSharedMemorySize, SM64);

    // 0) prep: A matrix + weight transpose/split (tiny)
    aprep_kernel<<<1, 256>>>(A_log);
    wprep_kernel<<<(128*512+255)/256, 256>>>(W_mix,  pWmixh, pWmixl, 512, 128, 128);
    wprep_kernel<<<(512*128+255)/256, 256>>>(W_in,   pWinh,  pWinl,  128, 512, 512);
    wprep_kernel<<<(64*256+255)/256,  256>>>(W_xproj,pWxph,  pWxpl,  256, 40,  64);
    wprep_kernel<<<(128*256+255)/256, 256>>>(W_op,   pWoph,  pWopl,  256, 128, 128);
    wprep_kernel<<<(256*128+255)/256, 256>>>(W_out,  pWouth, pWoutl, 128, 256, 256);

    // 1) H = [x|qk] @ W_mix + b_mix           (K=512, N=128)
    gemm_mma<128,true><<<dim3(TT/128, 1), 256, SM128>>>(
        x, qk, pWmixh, pWmixl, b_mix, pH, 512, DM, DM);

    // 2) XZ = H @ W_in + b_in                 (K=128, N=512)
    gemm_mma<128,false><<<dim3(TT/128, 4), 256, SM128>>>(
        pH, nullptr, pWinh, pWinl, b_in, pXZ, 128, 2*DI, 2*DI);

    // 3) conv + silu -> XC
    conv_silu_kernel<<<(TT*DI)/256, 256>>>(conv_w, conv_b);

    // 4) DBL = XC @ W_xproj                   (K=256, N=40 padded 64)
    gemm_mma<64,false><<<dim3(TT/128, 1), 256, SM64>>>(
        pXC, nullptr, pWxph, pWxpl, nullptr, pDBL, 256, 40, 40);

    // 5) dt
    dt_kernel<<<(TT*DI)/256, 256>>>(W_dt, b_dt);

    // 6-8) chunked selective scan
    scan_pass1  <<<BB*NC, 256>>>();
    scan_combine<<<(BB*DI*DS)/256, 256>>>();
    scan_pass2  <<<BB*NC, 256>>>(D_param);

    // 9) O1 = Y @ W_op + b_op                 (K=256, N=128)
    gemm_mma<128,false><<<dim3(TT/128, 1), 256, SM128>>>(
        pY, nullptr, pWoph, pWopl, b_op, pO1, 256, DM, DM);

    // 10) out = O1 @ W_out + b_out            (K=128, N=256)
    gemm_mma<128,false><<<dim3(TT/128, 2), 256, SM128>>>(
        pO1, nullptr, pWouth, pWoutl, b_out, out, 128, CC, CC);
}

// round 15
// speedup vs baseline: 1.8602x; 1.0686x over previous
#include <cuda_runtime.h>
#include <cuda_bf16.h>
#include <cstdint>

// ---------------- problem constants ----------------
#define BB 16
#define LL 4096
#define CC 256
#define DM 128            // d_model
#define DI 256            // d_inner
#define DS 16             // d_state
#define DR 8              // dt_rank
#define KCV 4             // conv kernel
#define TT (BB*LL)        // 65536 tokens
#define CH 128            // scan chunk length
#define NC (LL/CH)        // 32 chunks per batch

// ---------------- scratch (device globals; no allocation allowed) ----------------
__device__ __align__(16) float g_H  [(size_t)TT*DM];        // mix output (fp32)
__device__ __align__(16) float g_XZ [(size_t)TT*(2*DI)];    // in-proj output (xc_raw | z)
__device__ __align__(16) float g_XC [(size_t)TT*DI];        // conv+silu output
__device__ __align__(16) float g_DBL[(size_t)TT*40];        // xproj output
__device__ __align__(16) float g_DT [(size_t)TT*DI];        // softplus dt
__device__ __align__(16) float g_Y  [(size_t)TT*DI];        // scan output (fp32)
__device__ __align__(16) float g_O1 [(size_t)TT*DM];        // op output (fp32)
// transposed + split weights: Wt[n,k] = W[k,n]
__device__ __align__(16) __nv_bfloat16 g_Wmix_h[DM*512],  g_Wmix_l[DM*512];
__device__ __align__(16) __nv_bfloat16 g_Win_h [512*DM],  g_Win_l [512*DM];
__device__ __align__(16) __nv_bfloat16 g_Wxp_h [64*DI],   g_Wxp_l [64*DI];
__device__ __align__(16) __nv_bfloat16 g_Wop_h [DM*DI],   g_Wop_l [DM*DI];
__device__ __align__(16) __nv_bfloat16 g_Wout_h[CC*DM],   g_Wout_l[CC*DM];
// scan scratch
__device__ float g_Hend[(size_t)BB*NC*DI*DS];
__device__ float g_Hin [(size_t)BB*NC*DI*DS];
__device__ float g_S   [(size_t)BB*NC*DI];
__device__ float g_A   [DI*DS];
__device__ int   g_Aflag[DI];

// ---------------- PTX helpers (sm_80-compatible; no 'a'-suffix features) ----------------
__device__ __forceinline__ uint32_t smem_to_u32(const void* p) {
    uint32_t a;
    asm("{ .reg .u64 t; cvta.to.shared.u64 t, %1; cvt.u32.u64 %0, t; }" : "=r"(a) : "l"(p));
    return a;
}
__device__ __forceinline__ void cp16(uint32_t s, const void* g) {
    asm volatile("cp.async.cg.shared.global [%0], [%1], 16;" :: "r"(s), "l"(g));
}
#define CP_COMMIT() asm volatile("cp.async.commit_group;" ::: "memory")
#define CP_WAIT(n)  asm volatile("cp.async.wait_group %0;" :: "n"(n) : "memory")

#define LDSM_X4(r, addr) \
    asm volatile("ldmatrix.sync.aligned.m8n8.x4.shared.b16 {%0,%1,%2,%3}, [%4];" \
        : "=r"((r)[0]), "=r"((r)[1]), "=r"((r)[2]), "=r"((r)[3]) : "r"(addr))

#define MMA16816(d, a, b0, b1) \
    asm volatile("mma.sync.aligned.m16n8k16.row.col.f32.bf16.bf16.f32 " \
        "{%0,%1,%2,%3}, {%4,%5,%6,%7}, {%8,%9}, {%0,%1,%2,%3};" \
        : "+f"((d)[0]), "+f"((d)[1]), "+f"((d)[2]), "+f"((d)[3]) \
        : "r"((a)[0]), "r"((a)[1]), "r"((a)[2]), "r"((a)[3]), "r"(b0), "r"(b1))

// ---------------- packed f32x2 helpers (scan) ----------------
__device__ __forceinline__ unsigned long long pack2(float lo, float hi){
    unsigned long long r; asm("mov.b64 %0,{%1,%2};" : "=l"(r) : "f"(lo), "f"(hi)); return r;
}
__device__ __forceinline__ float2 unpack2(unsigned long long v){
    float2 r; asm("mov.b64 {%0,%1},%2;" : "=f"(r.x), "=f"(r.y) : "l"(v)); return r;
}
__device__ __forceinline__ unsigned long long mul2(unsigned long long a, unsigned long long b){
    unsigned long long d; asm("mul.rn.f32x2 %0,%1,%2;" : "=l"(d) : "l"(a), "l"(b)); return d;
}
__device__ __forceinline__ unsigned long long fma2(unsigned long long a, unsigned long long b, unsigned long long c){
    unsigned long long d; asm("fma.rn.f32x2 %0,%1,%2,%3;" : "=l"(d) : "l"(a), "l"(b), "l"(c)); return d;
}

__device__ __forceinline__ void split_bf16(float v, __nv_bfloat16& h, __nv_bfloat16& l) {
    h = __float2bfloat16(v);
    l = __float2bfloat16(v - __bfloat162float(h));
}
__device__ __forceinline__ uint32_t pack_bf(__nv_bfloat16 a, __nv_bfloat16 b) {
    uint16_t ua = *reinterpret_cast<uint16_t*>(&a);
    uint16_t ub = *reinterpret_cast<uint16_t*>(&b);
    return (uint32_t)ua | ((uint32_t)ub << 16);
}

// =====================================================================
// mma.sync split GEMM, fp32 A in global: C[m,n] = sum_k A[m,k]*Wt[n,k] + bias
// Per K=32 chunk: load A fp32 ONCE (register-staged), split to Ah/Al smem;
// cp.async pre-split weight tiles Bh/Bl; 3 segment MMA passes
// (Ah*Bh + Ah*Bl + Al*Bh) from one smem residency. fp32 accumulate.
// CTA: 64 x NT tile, 8 warps (2x4), warp tile 32 x NT/4, double-buffered.
// 2 CTAs/SM (launch_bounds) so one CTA's MMAs cover the other's
// split/sync serial sections.
// =====================================================================
template<int NT, bool CONCAT>
__global__ __launch_bounds__(256, 2)
void gemm_mma(const float* __restrict__ A0, const float* __restrict__ A1,
              const __nv_bfloat16* __restrict__ Bh, const __nv_bfloat16* __restrict__ Bl,
              const float* __restrict__ bias, float* __restrict__ Cf,
              int K, int Nout, int Nclip)
{
    constexpr int NTW = NT / 4;          // warp n-tile: 32 or 16
    constexpr int NF  = NTW / 8;         // n-frags per warp: 4 or 2
    constexpr int LDA = 40;              // padded row (elements)
    constexpr uint32_t ABUF = 64*LDA*2;  // bytes per A buffer (5120)
    constexpr uint32_t BBUF = NT*LDA*2;  // bytes per B buffer

    extern __shared__ char dsm[];
    const uint32_t sAh = smem_to_u32(dsm);
    const uint32_t sAl = sAh + 2*ABUF;
    const uint32_t sBh = sAl + 2*ABUF;
    const uint32_t sBl = sBh + 2*BBUF;

    const int tid  = threadIdx.x;
    const int lane = tid & 31;
    const int w    = tid >> 5;
    const int wm   = w >> 2;             // 0..1 -> 32-row halves
    const int wn   = w & 3;
    const int m0   = blockIdx.x * 64;
    const int n0   = blockIdx.y * NT;

    float acc[2][NF][4];
#pragma unroll
    for (int i = 0; i < 2; i++)
#pragma unroll
        for (int j = 0; j < NF; j++)
#pragma unroll
            for (int e = 0; e < 4; e++) acc[i][j][e] = 0.f;

    const int NCH = K >> 5;              // K=32 chunks
    float4 av[2];                        // register-staged A chunk (8 fp32/thread)

    // ---- loaders ----
    auto ldg_A = [&](int kk) {
        const int k0 = kk << 5;
#pragma unroll
        for (int q = 0; q < 2; ++q) {
            int c = tid + q*256;
            int row = c >> 3, sg = c & 7;
            int gk = k0 + sg*4;
            const float* src;
            if (CONCAT) src = (gk < 256) ? A0 + (size_t)(m0+row)*256 + gk
                                         : A1 + (size_t)(m0+row)*256 + (gk-256);
            else        src = A0 + (size_t)(m0+row)*K + gk;
            av[q] = *reinterpret_cast<const float4*>(src);
        }
    };
    auto sts_A = [&](int buf) {
#pragma unroll
        for (int q = 0; q < 2; ++q) {
            int c = tid + q*256;
            int row = c >> 3, sg = c & 7;
            __nv_bfloat16 h0,l0,h1,l1,h2,l2,h3,l3;
            split_bf16(av[q].x, h0, l0); split_bf16(av[q].y, h1, l1);
            split_bf16(av[q].z, h2, l2); split_bf16(av[q].w, h3, l3);
            uint32_t off = (uint32_t)(row*LDA + sg*4)*2;
            uint2 hv = { pack_bf(h0,h1), pack_bf(h2,h3) };
            uint2 lv = { pack_bf(l0,l1), pack_bf(l2,l3) };
            *reinterpret_cast<uint2*>(dsm + buf*ABUF + off) = hv;
            *reinterpret_cast<uint2*>(dsm + 2*ABUF + buf*ABUF + off) = lv;
        }
    };
    auto cpa_B = [&](int kk, int buf) {
        const int k0 = kk << 5;
#pragma unroll
        for (int q = 0; q < NT/64; ++q) {
            int c = tid + q*256;
            int row = c >> 2, sg = c & 3;
            cp16(sBh + buf*BBUF + (uint32_t)(row*LDA + sg*8)*2,
                 Bh + (size_t)(n0+row)*K + k0 + sg*8);
        }
#pragma unroll
        for (int q = 0; q < NT/64; ++q) {
            int c = tid + q*256;
            int row = c >> 2, sg = c & 3;
            cp16(sBl + buf*BBUF + (uint32_t)(row*LDA + sg*8)*2,
                 Bl + (size_t)(n0+row)*K + k0 + sg*8);
        }
        CP_COMMIT();
    };

    // ---- prologue: chunk 0 into buf 0 ----
    ldg_A(0);
    cpa_B(0, 0);
    sts_A(0);
    CP_WAIT(0);
    __syncthreads();

    int buf = 0;
#pragma unroll 1
    for (int it = 0; it < NCH; ++it) {
        const bool more = (it + 1 < NCH);
        if (more) { ldg_A(it + 1); cpa_B(it + 1, buf ^ 1); }

        // ---- compute: 3 segments from this chunk ----
#pragma unroll
        for (int ks = 0; ks < 2; ++ks) {
            uint32_t a[2][4];
            uint32_t bh[NF][2], bl[NF][2];
#pragma unroll
            for (int mf = 0; mf < 2; ++mf) {
                uint32_t addr = sAh + buf*ABUF +
                    (uint32_t)((wm*32 + mf*16 + (lane & 15))*LDA + ks*16 + ((lane >> 4) << 3))*2;
                LDSM_X4(a[mf], addr);
            }
#pragma unroll
            for (int nf2 = 0; nf2 < NF/2; ++nf2) {
                uint32_t r[4];
                uint32_t addr = sBh + buf*BBUF +
                    (uint32_t)((wn*NTW + nf2*16 + ((lane >> 4) << 3) + (lane & 7))*LDA
                               + ks*16 + (((lane >> 3) & 1) << 3))*2;
                LDSM_X4(r, addr);
                bh[2*nf2][0] = r[0]; bh[2*nf2][1] = r[1];
                bh[2*nf2+1][0] = r[2]; bh[2*nf2+1][1] = r[3];
            }
#pragma unroll
            for (int nf2 = 0; nf2 < NF/2; ++nf2) {
                uint32_t r[4];
                uint32_t addr = sBl + buf*BBUF +
                    (uint32_t)((wn*NTW + nf2*16 + ((lane >> 4) << 3) + (lane & 7))*LDA
                               + ks*16 + (((lane >> 3) & 1) << 3))*2;
                LDSM_X4(r, addr);
                bl[2*nf2][0] = r[0]; bl[2*nf2][1] = r[1];
                bl[2*nf2+1][0] = r[2]; bl[2*nf2+1][1] = r[3];
            }
            // seg0: Ah*Bh ; seg1: Ah*Bl
#pragma unroll
            for (int mf = 0; mf < 2; ++mf)
#pragma unroll
                for (int nf = 0; nf < NF; ++nf) {
                    MMA16816(acc[mf][nf], a[mf], bh[nf][0], bh[nf][1]);
                    MMA16816(acc[mf][nf], a[mf], bl[nf][0], bl[nf][1]);
                }
            // seg2: Al*Bh (reload a from Al)
#pragma unroll
            for (int mf = 0; mf < 2; ++mf) {
                uint32_t addr = sAl + buf*ABUF +
                    (uint32_t)((wm*32 + mf*16 + (lane & 15))*LDA + ks*16 + ((lane >> 4) << 3))*2;
                LDSM_X4(a[mf], addr);
            }
#pragma unroll
            for (int mf = 0; mf < 2; ++mf)
#pragma unroll
                for (int nf = 0; nf < NF; ++nf)
                    MMA16816(acc[mf][nf], a[mf], bh[nf][0], bh[nf][1]);
        }

        if (more) {
            sts_A(buf ^ 1);
            CP_WAIT(0);
            __syncthreads();
            buf ^= 1;
        }
    }

    // ---- epilogue (fp32 + bias) ----
#pragma unroll
    for (int mf = 0; mf < 2; ++mf) {
        const int r0 = m0 + wm*32 + mf*16 + (lane >> 2);
#pragma unroll
        for (int nf = 0; nf < NF; ++nf) {
            const int c0 = n0 + wn*NTW + nf*8 + ((lane & 3) << 1);
#pragma unroll
            for (int half = 0; half < 2; ++half) {
                const int row = r0 + half*8;
                if (c0 < Nclip)
                    Cf[(size_t)row*Nout + c0]     = acc[mf][nf][2*half]   + (bias ? bias[c0]   : 0.f);
                if (c0 + 1 < Nclip)
                    Cf[(size_t)row*Nout + c0 + 1] = acc[mf][nf][2*half+1] + (bias ? bias[c0+1] : 0.f);
            }
        }
    }
}

// ---------------- prep kernels ----------------
__global__ __launch_bounds__(256)
void wprep_kernel(const float* __restrict__ W, __nv_bfloat16* __restrict__ Wh,
                  __nv_bfloat16* __restrict__ Wl, int K, int N, int NP)
{
    int idx = blockIdx.x*256 + threadIdx.x;
    if (idx >= NP*K) return;
    int n = idx / K, k = idx % K;
    float v = (n < N) ? W[(size_t)k*N + n] : 0.f;
    __nv_bfloat16 h, l; split_bf16(v, h, l);
    Wh[idx] = h; Wl[idx] = l;
}

// ---------------- A_log preprocessing ----------------
__global__ void aprep_kernel(const float* __restrict__ A_log)
{
    int d = threadIdx.x;
    if (d >= DI) return;
    float Av[DS];
#pragma unroll
    for (int s = 0; s < DS; s++) { Av[s] = -__expf(A_log[d*DS + s]); g_A[d*DS + s] = Av[s]; }
    int ok = 1;
#pragma unroll
    for (int s = 0; s < DS; s++) {
        float tgt = Av[0] * (float)(s+1);
        if (fabsf(Av[s] - tgt) > 1e-5f * fabsf(Av[s]) + 1e-7f) ok = 0;
    }
    g_Aflag[d] = ok;
}

// ---------------- depthwise conv (K=4, causal) + SiLU ----------------
__global__ __launch_bounds__(256)
void conv_silu_kernel(const float* __restrict__ conv_w, const float* __restrict__ conv_b)
{
    int idx = blockIdx.x * 256 + threadIdx.x;   // over T*DI
    int d = idx & (DI-1);
    int t = idx >> 8;
    int l = t & (LL-1);
    float acc = conv_b[d];
#pragma unroll
    for (int k = 0; k < KCV; k++) {
        int lt = l - (KCV-1) + k;
        if (lt >= 0) acc += g_XZ[(size_t)(t - (KCV-1) + k)*(2*DI) + d] * conv_w[d*KCV + k];
    }
    float sig = 1.f / (1.f + __expf(-acc));
    g_XC[idx] = acc * sig;
}

// ---------------- dt = softplus(dbl[:, :8] @ W_dt + b_dt) ----------------
__global__ __launch_bounds__(256)
void dt_kernel(const float* __restrict__ W_dt, const float* __restrict__ b_dt)
{
    int idx = blockIdx.x * 256 + threadIdx.x;   // over T*DI
    int d = idx & (DI-1);
    int t = idx >> 8;
    float acc = b_dt[d];
    const float* dbl = g_DBL + (size_t)t*40;
#pragma unroll
    for (int r = 0; r < DR; r++) acc += dbl[r] * W_dt[r*DI + d];
    float sp = (acc > 20.f) ? acc : log1pf(__expf(acc));
    g_DT[idx] = sp;
}

// ---------------- scan pass 1 ----------------
__global__ __launch_bounds__(256)
void scan_pass1()
{
    __shared__ float sB[CH][DS];
    const int bc = blockIdx.x;
    const int b = bc / NC, c = bc % NC;
    const int d = threadIdx.x;
    const int tok0 = b*LL + c*CH;

#pragma unroll
    for (int q = 0; q < (CH*DS)/256; q++) {
        int e = threadIdx.x + q*256;
        int j = e % DS, st = e / DS;
        sB[st][j] = g_DBL[(size_t)(tok0+st)*40 + 8 + j];
    }
    __syncthreads();

    const float A0 = g_A[d*DS];
    const int fast = g_Aflag[d];
    float S = 0.f;

    if (fast) {
        unsigned long long h2[DS/2];
#pragma unroll
        for (int sp = 0; sp < DS/2; sp++) h2[sp] = 0ULL;
        for (int st = 0; st < CH; st++) {
            int idx = (tok0+st)*DI + d;
            float dt = g_DT[idx];
            float x  = g_XC[idx];
            S += dt;
            float e1 = __expf(dt * A0);
            float e2 = e1 * e1;
            unsigned long long p2  = pack2(e1, e2);
            unsigned long long e22 = pack2(e2, e2);
            float dtx = dt * x;
            unsigned long long dtx2 = pack2(dtx, dtx);
            const unsigned long long* Bp = reinterpret_cast<const unsigned long long*>(sB[st]);
#pragma unroll
            for (int sp = 0; sp < DS/2; sp++) {
                h2[sp] = fma2(p2, h2[sp], mul2(dtx2, Bp[sp]));
                p2 = mul2(p2, e22);
            }
        }
        float* He = g_Hend + ((size_t)bc*DI + d)*DS;
#pragma unroll
        for (int sp = 0; sp < DS/2; sp++) {
            float2 v = unpack2(h2[sp]);
            He[2*sp] = v.x; He[2*sp+1] = v.y;
        }
    } else {
        float Av[DS], h[DS];
#pragma unroll
        for (int s = 0; s < DS; s++) { Av[s] = g_A[d*DS + s]; h[s] = 0.f; }
        for (int st = 0; st < CH; st++) {
            int idx = (tok0+st)*DI + d;
            float dt = g_DT[idx];
            float x  = g_XC[idx];
            S += dt;
            float dtx = dt * x;
#pragma unroll
            for (int s = 0; s < DS; s++) {
                float a = __expf(dt * Av[s]);
                h[s] = a*h[s] + dtx * sB[st][s];
            }
        }
        float* He = g_Hend + ((size_t)bc*DI + d)*DS;
#pragma unroll
        for (int s = 0; s < DS; s++) He[s] = h[s];
    }
    g_S[(size_t)bc*DI + d] = S;
}

// ---------------- inter-chunk combine ----------------
__global__ __launch_bounds__(256)
void scan_combine()
{
    int g = blockIdx.x * 256 + threadIdx.x;
    int s = g & (DS-1);
    int d = (g >> 4) & (DI-1);
    int b = g >> 12;
    float Av = g_A[d*DS + s];
    float h = 0.f;
    for (int c = 0; c < NC; c++) {
        size_t base = ((size_t)(b*NC + c)*DI + d)*DS + s;
        g_Hin[base] = h;
        float S = g_S[(size_t)(b*NC + c)*DI + d];
        h = __expf(Av * S) * h + g_Hend[base];
    }
}

// ---------------- scan pass 2: emit y=(scan + xc*D)*silu(z), fp32 ----------------
__global__ __launch_bounds__(256)
void scan_pass2(const float* __restrict__ D_param)
{
    __shared__ float sBC[CH][2*DS];
    const int bc = blockIdx.x;
    const int b = bc / NC, c = bc % NC;
    const int d = threadIdx.x;
    const int tok0 = b*LL + c*CH;

#pragma unroll
    for (int q = 0; q < (CH*2*DS)/256; q++) {
        int e = threadIdx.x + q*256;
        int j = e & (2*DS - 1), st = e >> 5;
        sBC[st][j] = g_DBL[(size_t)(tok0+st)*40 + 8 + j];
    }
    __syncthreads();

    const float A0 = g_A[d*DS];
    const int fast = g_Aflag[d];
    const float Dp = D_param[d];
    const size_t hbase = ((size_t)bc*DI + d)*DS;

    if (fast) {
        unsigned long long h2[DS/2];
#pragma unroll
        for (int sp = 0; sp < DS/2; sp++)
            h2[sp] = pack2(g_Hin[hbase + 2*sp], g_Hin[hbase + 2*sp + 1]);
        for (int st = 0; st < CH; st++) {
            int idx = (tok0+st)*DI + d;
            float dt = g_DT[idx];
            float x  = g_XC[idx];
            float e1 = __expf(dt * A0);
            float e2 = e1 * e1;
            unsigned long long p2  = pack2(e1, e2);
            unsigned long long e22 = pack2(e2, e2);
            float dtx = dt * x;
            unsigned long long dtx2 = pack2(dtx, dtx);
            const unsigned long long* BCp = reinterpret_cast<const unsigned long long*>(sBC[st]);
            unsigned long long y2 = 0ULL;
#pragma unroll
            for (int sp = 0; sp < DS/2; sp++) {
                h2[sp] = fma2(p2, h2[sp], mul2(dtx2, BCp[sp]));
                y2 = fma2(h2[sp], BCp[DS/2 + sp], y2);
                p2 = mul2(p2, e22);
            }
            float2 yv = unpack2(y2);
            float y = yv.x + yv.y;
            float z = g_XZ[(size_t)(tok0+st)*(2*DI) + DI + d];
            float sz = z / (1.f + __expf(-z));
            g_Y[idx] = (y + x*Dp) * sz;
        }
    } else {
        float Av[DS], h[DS];
#pragma unroll
        for (int s = 0; s < DS; s++) { Av[s] = g_A[d*DS + s]; h[s] = g_Hin[hbase + s]; }
        for (int st = 0; st < CH; st++) {
            int idx = (tok0+st)*DI + d;
            float dt = g_DT[idx];
            float x  = g_XC[idx];
            float dtx = dt * x;
            float y = 0.f;
#pragma unroll
            for (int s = 0; s < DS; s++) {
                float a = __expf(dt * Av[s]);
                h[s] = a*h[s] + dtx * sBC[st][s];
                y += h[s] * sBC[st][DS + s];
            }
            float z = g_XZ[(size_t)(tok0+st)*(2*DI) + DI + d];
            float sz = z / (1.f + __expf(-z));
            g_Y[idx] = (y + x*Dp) * sz;
        }
    }
}

// ---------------- host launch ----------------
extern "C" void kernel_launch(void* const* d_in, const int* in_sizes, int n_in,
                              void* d_out, int out_size)
{
    const float* x      = (const float*)d_in[0];
    const float* qk     = (const float*)d_in[1];
    const float* W_mix  = (const float*)d_in[2];
    const float* b_mix  = (const float*)d_in[3];
    const float* W_in   = (const float*)d_in[4];
    const float* b_in   = (const float*)d_in[5];
    const float* conv_w = (const float*)d_in[6];
    const float* conv_b = (const float*)d_in[7];
    const float* W_xproj= (const float*)d_in[8];
    const float* W_dt   = (const float*)d_in[9];
    const float* b_dt   = (const float*)d_in[10];
    const float* A_log  = (const float*)d_in[11];
    const float* D_param= (const float*)d_in[12];
    const float* W_op   = (const float*)d_in[13];
    const float* b_op   = (const float*)d_in[14];
    const float* W_out  = (const float*)d_in[15];
    const float* b_out  = (const float*)d_in[16];
    float* out = (float*)d_out;

    // symbol addresses
    float *pH,*pXZ,*pXC,*pDBL,*pY,*pO1;
    __nv_bfloat16 *pWmixh,*pWmixl,*pWinh,*pWinl,*pWxph,*pWxpl,*pWoph,*pWopl,*pWouth,*pWoutl;
    cudaGetSymbolAddress((void**)&pH,  g_H);
    cudaGetSymbolAddress((void**)&pXZ, g_XZ);
    cudaGetSymbolAddress((void**)&pXC, g_XC);
    cudaGetSymbolAddress((void**)&pDBL,g_DBL);
    cudaGetSymbolAddress((void**)&pY,  g_Y);
    cudaGetSymbolAddress((void**)&pO1, g_O1);
    cudaGetSymbolAddress((void**)&pWmixh, g_Wmix_h);cudaGetSymbolAddress((void**)&pWmixl, g_Wmix_l);
    cudaGetSymbolAddress((void**)&pWinh, g_Win_h);  cudaGetSymbolAddress((void**)&pWinl, g_Win_l);
    cudaGetSymbolAddress((void**)&pWxph, g_Wxp_h);  cudaGetSymbolAddress((void**)&pWxpl, g_Wxp_l);
    cudaGetSymbolAddress((void**)&pWoph, g_Wop_h);  cudaGetSymbolAddress((void**)&pWopl, g_Wop_l);
    cudaGetSymbolAddress((void**)&pWouth, g_Wout_h);cudaGetSymbolAddress((void**)&pWoutl, g_Wout_l);

    constexpr int SM128 = 4*(64*40*2) + 4*(128*40*2);   // A + B buffers: 61440
    constexpr int SM64  = 4*(64*40*2) + 4*(64*40*2);    // 40960
    cudaFuncSetAttribute(gemm_mma<128,true>,  cudaFuncAttributeMaxDynamicSharedMemorySize, SM128);
    cudaFuncSetAttribute(gemm_mma<128,false>, cudaFuncAttributeMaxDynamicSharedMemorySize, SM128);
    cudaFuncSetAttribute(gemm_mma<64,false>,  cudaFuncAttributeMaxDynamicSharedMemorySize, SM64);

    // 0) prep: A matrix + weight transpose/split (tiny)
    aprep_kernel<<<1, 256>>>(A_log);
    wprep_kernel<<<(128*512+255)/256, 256>>>(W_mix,  pWmixh, pWmixl, 512, 128, 128);
    wprep_kernel<<<(512*128+255)/256, 256>>>(W_in,   pWinh,  pWinl,  128, 512, 512);
    wprep_kernel<<<(64*256+255)/256,  256>>>(W_xproj,pWxph,  pWxpl,  256, 40,  64);
    wprep_kernel<<<(128*256+255)/256, 256>>>(W_op,   pWoph,  pWopl,  256, 128, 128);
    wprep_kernel<<<(256*128+255)/256, 256>>>(W_out,  pWouth, pWoutl, 128, 256, 256);

    // 1) H = [x|qk] @ W_mix + b_mix           (K=512, N=128)
    gemm_mma<128,true><<<dim3(TT/64, 1), 256, SM128>>>(
        x, qk, pWmixh, pWmixl, b_mix, pH, 512, DM, DM);

    // 2) XZ = H @ W_in + b_in                 (K=128, N=512)
    gemm_mma<128,false><<<dim3(TT/64, 4), 256, SM128>>>(
        pH, nullptr, pWinh, pWinl, b_in, pXZ, 128, 2*DI, 2*DI);

    // 3) conv + silu -> XC
    conv_silu_kernel<<<(TT*DI)/256, 256>>>(conv_w, conv_b);

    // 4) DBL = XC @ W_xproj                   (K=256, N=40 padded 64)
    gemm_mma<64,false><<<dim3(TT/64, 1), 256, SM64>>>(
        pXC, nullptr, pWxph, pWxpl, nullptr, pDBL, 256, 40, 40);

    // 5) dt
    dt_kernel<<<(TT*DI)/256, 256>>>(W_dt, b_dt);

    // 6-8) chunked selective scan
    scan_pass1  <<<BB*NC, 256>>>();
    scan_combine<<<(BB*DI*DS)/256, 256>>>();
    scan_pass2  <<<BB*NC, 256>>>(D_param);

    // 9) O1 = Y @ W_op + b_op                 (K=256, N=128)
    gemm_mma<128,false><<<dim3(TT/64, 1), 256, SM128>>>(
        pY, nullptr, pWoph, pWopl, b_op, pO1, 256, DM, DM);

    // 10) out = O1 @ W_out + b_out            (K=128, N=256)
    gemm_mma<128,false><<<dim3(TT/64, 2), 256, SM128>>>(
        pO1, nullptr, pWouth, pWoutl, b_out, out, 128, CC, CC);
}